// round 14
// baseline (speedup 1.0000x reference)
#include <cuda_runtime.h>
#include <cuda_bf16.h>
#include <math.h>
#include <stdint.h>

#define D_ 1024
#define L_ 2048
#define B_ 2

typedef __nv_bfloat16 bf16;

// GEMM: CTA 128x256, 512 thr, warps 4M x 4N (32x64 each), KC=64, 2-stage cp.async
#define STG_BYTES 98304
#define GEMM_SMEM (2 * STG_BYTES + 1024)

// ---------------- fp32 scratch ----------------
__device__ float g_x [B_ * L_ * D_];
__device__ float g_t2[B_ * L_ * 2 * D_];
__device__ float g_q [B_ * L_ * D_];
__device__ float g_s [4LL * L_ * 4096];   // scores; after rowsoft reused for split-K partials

// ---------------- bf16 hi/lo planes ----------------
__device__ __align__(16) bf16 p_t1h [B_ * L_ * D_],       p_t1l [B_ * L_ * D_];
__device__ __align__(16) bf16 p_xh  [B_ * L_ * D_],       p_xl  [B_ * L_ * D_];
__device__ __align__(16) bf16 p_qkvh[B_ * L_ * 3072],     p_qkvl[B_ * L_ * 3072];
__device__ __align__(16) bf16 p_kph [B_ * 2 * L_ * 512],  p_kpl [B_ * 2 * L_ * 512];
__device__ __align__(16) bf16 p_vth [B_ * 512 * 2 * L_],  p_vtl [B_ * 512 * 2 * L_];
__device__ __align__(16) bf16 p_Ph  [4LL * L_ * 4096],    p_Pl  [4LL * L_ * 4096];
__device__ __align__(16) bf16 p_Wh  [12 * 1024 * 1024],   p_Wl  [12 * 1024 * 1024];

struct Batch8 {
    long long offA[8];
    long long offB[8];
    long long offC[8];
    float alpha[8];
};

// ---------------- helpers ----------------
__device__ __forceinline__ uint32_t smem_u32(const void* p) {
    uint32_t a;
    asm("{ .reg .u64 t; cvta.to.shared.u64 t, %1; cvt.u32.u64 %0, t; }" : "=r"(a) : "l"(p));
    return a;
}
__device__ __forceinline__ void split2(float a, float b, uint32_t& hi, uint32_t& lo) {
    uint32_t h;
    asm("cvt.rn.satfinite.bf16x2.f32 %0, %1, %2;" : "=r"(h) : "f"(b), "f"(a));
    float ra = a - __uint_as_float(h << 16);
    float rb = b - __uint_as_float(h & 0xffff0000u);
    uint32_t l;
    asm("cvt.rn.satfinite.bf16x2.f32 %0, %1, %2;" : "=r"(l) : "f"(rb), "f"(ra));
    hi = h; lo = l;
}
__device__ __forceinline__ void split1(float a, bf16& h, bf16& l) {
    h = __float2bfloat16_rn(a);
    l = __float2bfloat16_rn(a - __bfloat162float(h));
}
// non-volatile: lets ptxas interleave HMMAs with LDSMs
__device__ __forceinline__ void mma_bf16(float* c, const uint32_t* a, uint32_t b0, uint32_t b1) {
    asm("mma.sync.aligned.m16n8k16.row.col.f32.bf16.bf16.f32 "
        "{%0,%1,%2,%3}, {%4,%5,%6,%7}, {%8,%9}, {%0,%1,%2,%3};"
        : "+f"(c[0]), "+f"(c[1]), "+f"(c[2]), "+f"(c[3])
        : "r"(a[0]), "r"(a[1]), "r"(a[2]), "r"(a[3]), "r"(b0), "r"(b1));
}
__device__ __forceinline__ void cpa16(uint32_t s, const bf16* g) {
    asm volatile("cp.async.cg.shared.global [%0], [%1], 16;"
                 :: "r"(s), "l"(__cvta_generic_to_global((const void*)g)) : "memory");
}
__device__ __forceinline__ void ldm4(uint32_t addr, uint32_t* r) {
    asm volatile("ldmatrix.sync.aligned.m8n8.x4.shared.b16 {%0,%1,%2,%3}, [%4];"
                 : "=r"(r[0]), "=r"(r[1]), "=r"(r[2]), "=r"(r[3]) : "r"(addr));
}

// block reductions for 256 threads: 1 barrier each (disjoint 8-word buffers)
__device__ __forceinline__ float blk_sum(float v, int tid, volatile float* red8) {
#pragma unroll
    for (int o = 16; o > 0; o >>= 1) v += __shfl_xor_sync(0xffffffffu, v, o);
    if ((tid & 31) == 0) red8[tid >> 5] = v;
    __syncthreads();
    float s = red8[tid & 7];
#pragma unroll
    for (int o = 4; o > 0; o >>= 1) s += __shfl_xor_sync(0xffffffffu, s, o);
    return s;
}
__device__ __forceinline__ float blk_max(float v, int tid, volatile float* red8) {
#pragma unroll
    for (int o = 16; o > 0; o >>= 1) v = fmaxf(v, __shfl_xor_sync(0xffffffffu, v, o));
    if ((tid & 31) == 0) red8[tid >> 5] = v;
    __syncthreads();
    float s = red8[tid & 7];
#pragma unroll
    for (int o = 4; o > 0; o >>= 1) s = fmaxf(s, __shfl_xor_sync(0xffffffffu, s, o));
    return s;
}

// ---------------- plane-operand GEMM: C = alpha * A(MxK) * B(NxK)^T ----------------
// Round-9 mainloop (verified optimum): single barrier per K-chunk.
__global__ __launch_bounds__(512, 1) void gemm_pp(
    const bf16* __restrict__ Ah, const bf16* __restrict__ Al,
    const bf16* __restrict__ Bh, const bf16* __restrict__ Bl,
    float* __restrict__ C, bf16* __restrict__ Ch, bf16* __restrict__ Cl,
    const float* __restrict__ bias,
    int K, int lda, int ldb, int ldc, Batch8 bt)
{
    extern __shared__ char dsm[];
    uint32_t base = smem_u32(dsm);
    base = (base + 1023u) & ~1023u;

    const int z = blockIdx.z;
    const bf16* gAh = Ah + bt.offA[z];
    const bf16* gAl = Al + bt.offA[z];
    const bf16* gBh = Bh + bt.offB[z];
    const bf16* gBl = Bl + bt.offB[z];
    const float alpha = bt.alpha[z];

    const int tid = threadIdx.x;
    const int lane = tid & 31;
    const int wid = tid >> 5;
    const int wm = wid >> 2, wn = wid & 3;
    const int bm = blockIdx.y * 128, bn = blockIdx.x * 256;

    // cp.async: per thread 4 A chunks (rows rowT+{0,32,64,96}) + 8 B chunks (+{0..224})
    const int rowT = tid >> 4;
    const int sub  = tid & 15;
    const int plane = sub >> 3;
    const int c4 = sub & 7;
    const bf16* aP = (plane ? gAl : gAh) + (size_t)(bm + rowT) * lda + c4 * 8;
    const bf16* bP = (plane ? gBl : gBh) + (size_t)(bn + rowT) * ldb + c4 * 8;
    const uint32_t swz = ((uint32_t)c4 * 16u) ^ (((uint32_t)rowT & 7u) << 4);
    const uint32_t sA = base + (uint32_t)rowT * 256u + (uint32_t)plane * 128u + swz;
    const uint32_t sB = base + 32768u + (uint32_t)rowT * 256u + (uint32_t)plane * 128u + swz;
    const size_t stepA = (size_t)32 * lda;
    const size_t stepB = (size_t)32 * ldb;

    // fragment addressing
    const int rA = lane & 15, khA = lane >> 4;
    const uint32_t abase = base + (uint32_t)(wm * 32 + rA) * 256u;
    const uint32_t swA = ((uint32_t)rA & 7u) << 4;
    const int rBr = (lane & 7) + ((lane >> 4) << 3);
    const int khB = (lane >> 3) & 1;
    const uint32_t bbase = base + 32768u + (uint32_t)(wn * 64 + rBr) * 256u;
    const uint32_t swB = ((uint32_t)rBr & 7u) << 4;

    float acc[2][8][4];
#pragma unroll
    for (int i = 0; i < 2; i++)
#pragma unroll
        for (int j = 0; j < 8; j++)
#pragma unroll
            for (int c = 0; c < 4; c++) acc[i][j][c] = 0.f;

    const int nk = K >> 6;

    // prologue: stage 0
#pragma unroll
    for (int i = 0; i < 4; i++) cpa16(sA + i * 8192u, aP + (size_t)i * stepA);
#pragma unroll
    for (int i = 0; i < 8; i++) cpa16(sB + i * 8192u, bP + (size_t)i * stepB);
    asm volatile("cp.async.commit_group;" ::: "memory");

    for (int kt = 0; kt < nk; kt++) {
        asm volatile("cp.async.wait_group 0;" ::: "memory");
        __syncthreads();
        if (kt + 1 < nk) {
            const uint32_t so2 = ((kt + 1) & 1) * (uint32_t)STG_BYTES;
            const int k0 = (kt + 1) << 6;
#pragma unroll
            for (int i = 0; i < 4; i++) cpa16(sA + so2 + i * 8192u, aP + k0 + (size_t)i * stepA);
#pragma unroll
            for (int i = 0; i < 8; i++) cpa16(sB + so2 + i * 8192u, bP + k0 + (size_t)i * stepB);
            asm volatile("cp.async.commit_group;" ::: "memory");
        }
        const uint32_t so = (kt & 1) * (uint32_t)STG_BYTES;
        const uint32_t ab = abase + so;
        const uint32_t bb = bbase + so;
#pragma unroll
        for (int s = 0; s < 4; s++) {
            const uint32_t aoff = ((uint32_t)((s * 2 + khA) * 16)) ^ swA;
            const uint32_t boff = ((uint32_t)((s * 2 + khB) * 16)) ^ swB;
            uint32_t ah[2][4], al[2][4];
#pragma unroll
            for (int mb = 0; mb < 2; mb++) {
                ldm4(ab + mb * 4096 + aoff, ah[mb]);
                ldm4(ab + mb * 4096 + 128 + aoff, al[mb]);
            }
#pragma unroll
            for (int half = 0; half < 2; half++) {
                uint32_t bh[2][4], bl[2][4];
#pragma unroll
                for (int p2 = 0; p2 < 2; p2++) {
                    const int pr = half * 2 + p2;
                    ldm4(bb + pr * 4096 + boff, bh[p2]);
                    ldm4(bb + pr * 4096 + 128 + boff, bl[p2]);
                }
                // P1: Ah x Bh (8 MMAs, distinct accumulators)
#pragma unroll
                for (int p2 = 0; p2 < 2; p2++)
#pragma unroll
                    for (int nb2 = 0; nb2 < 2; nb2++)
#pragma unroll
                        for (int mb = 0; mb < 2; mb++)
                            mma_bf16(acc[mb][(half * 2 + p2) * 2 + nb2],
                                     ah[mb], bh[p2][nb2 * 2], bh[p2][nb2 * 2 + 1]);
                // P2: Ah x Bl
#pragma unroll
                for (int p2 = 0; p2 < 2; p2++)
#pragma unroll
                    for (int nb2 = 0; nb2 < 2; nb2++)
#pragma unroll
                        for (int mb = 0; mb < 2; mb++)
                            mma_bf16(acc[mb][(half * 2 + p2) * 2 + nb2],
                                     ah[mb], bl[p2][nb2 * 2], bl[p2][nb2 * 2 + 1]);
                // P3: Al x Bh
#pragma unroll
                for (int p2 = 0; p2 < 2; p2++)
#pragma unroll
                    for (int nb2 = 0; nb2 < 2; nb2++)
#pragma unroll
                        for (int mb = 0; mb < 2; mb++)
                            mma_bf16(acc[mb][(half * 2 + p2) * 2 + nb2],
                                     al[mb], bh[p2][nb2 * 2], bh[p2][nb2 * 2 + 1]);
            }
        }
    }

    // ---- epilogue ----
    const int qr = lane >> 2, qc = lane & 3;
    if (Ch) {
#pragma unroll
        for (int mb = 0; mb < 2; mb++) {
            const int row = bm + wm * 32 + mb * 16 + qr;
#pragma unroll
            for (int nb = 0; nb < 8; nb++) {
                const int col = bn + wn * 64 + nb * 8 + qc * 2;
                uint32_t h0, l0, h1, l1;
                split2(acc[mb][nb][0] * alpha, acc[mb][nb][1] * alpha, h0, l0);
                split2(acc[mb][nb][2] * alpha, acc[mb][nb][3] * alpha, h1, l1);
                const long long o0 = bt.offC[z] + (long long)row * ldc + col;
                const long long o1 = bt.offC[z] + (long long)(row + 8) * ldc + col;
                *(uint32_t*)(Ch + o0) = h0; *(uint32_t*)(Cl + o0) = l0;
                *(uint32_t*)(Ch + o1) = h1; *(uint32_t*)(Cl + o1) = l1;
            }
        }
    } else {
        float* Cz = C + bt.offC[z];
#pragma unroll
        for (int mb = 0; mb < 2; mb++) {
            const int row = bm + wm * 32 + mb * 16 + qr;
#pragma unroll
            for (int nb = 0; nb < 8; nb++) {
                const int col = bn + wn * 64 + nb * 8 + qc * 2;
                float2 v0, v1;
                v0.x = acc[mb][nb][0] * alpha;
                v0.y = acc[mb][nb][1] * alpha;
                v1.x = acc[mb][nb][2] * alpha;
                v1.y = acc[mb][nb][3] * alpha;
                if (bias) {
                    float2 bv = *(const float2*)(bias + col);
                    v0.x += bv.x; v0.y += bv.y;
                    v1.x += bv.x; v1.y += bv.y;
                }
                *(float2*)(Cz + (size_t)row * ldc + col) = v0;
                *(float2*)(Cz + (size_t)(row + 8) * ldc + col) = v1;
            }
        }
    }
}

// ---------------- split-K combine: t1 planes = split(p0 + p1) ----------------
// partials: [kh][bg][l][dd(512)] fp32 in g_s; output t1 planes [b*L + l][g*512 + dd]
__global__ __launch_bounds__(256) void k_combine(
    const float* __restrict__ part, bf16* __restrict__ oh, bf16* __restrict__ ol)
{
    int i = blockIdx.x * 256 + threadIdx.x;   // float4 index, 1048576 total
    const float4 v0 = ((const float4*)part)[i];
    const float4 v1 = ((const float4*)part)[i + 1048576];
    float a = v0.x + v1.x, b = v0.y + v1.y, c = v0.z + v1.z, d = v0.w + v1.w;
    uint32_t h0, l0, h1, l1;
    split2(a, b, h0, l0);
    split2(c, d, h1, l1);
    const int bg = i >> 18;           // L_*512/4 = 262144
    const int r = i & 262143;
    const int l = r >> 7;             // 512/4 = 128
    const int dd4 = r & 127;
    const int dst = ((bg >> 1) * 2048 + l) * 256 + (bg & 1) * 128 + dd4;  // uint2 units
    ((uint2*)oh)[dst] = make_uint2(h0, h1);
    ((uint2*)ol)[dst] = make_uint2(l0, l1);
}

// ---------------- weight split, layout: pw0|pw1 | (q0,kv0)|(q1,kv1) | ow0|ow1 ----------------
__global__ __launch_bounds__(256) void k_splitall(
    const float* __restrict__ pww, const float* __restrict__ qw,
    const float* __restrict__ kvw, const float* __restrict__ ow,
    bf16* __restrict__ h, bf16* __restrict__ l)
{
    long long i = (long long)blockIdx.x * 256 + threadIdx.x;
    const float* src;
    long long s;
    if (i < 1048576) { src = pww; s = i; }
    else if (i < 2621440) {
        long long j = i - 1048576;
        int layer = (int)(j / 786432);
        long long r = j - (long long)layer * 786432;
        if (r < 262144) { src = qw;  s = (long long)layer * 262144 + r; }
        else            { src = kvw; s = (long long)layer * 524288 + (r - 262144); }
    }
    else { src = ow; s = i - 2621440; }
    float4 v = ((const float4*)src)[s];
    uint32_t h0, l0, h1, l1;
    split2(v.x, v.y, h0, l0);
    split2(v.z, v.w, h1, l1);
    ((uint2*)h)[i] = make_uint2(h0, h1);
    ((uint2*)l)[i] = make_uint2(l0, l1);
}

// ---------------- Julia embedding ----------------
__global__ __launch_bounds__(256) void k_embed(
    const int* __restrict__ tok, const float* __restrict__ ctab,
    const float* __restrict__ projw, const float* __restrict__ escale,
    float* __restrict__ x)
{
    int bl = blockIdx.x;
    int t = tok[bl];
    float cr = ctab[2 * t], ci = ctab[2 * t + 1];
    float f[16];
    float zr = 0.f, zi = 0.f;
#pragma unroll
    for (int s = 0; s < 8; s++) {
        float nr = zr * zr - zi * zi + cr;
        float ni = 2.f * zr * zi + ci;
        zr = nr; zi = ni;
        f[2 * s] = zr; f[2 * s + 1] = zi;
    }
    float es = escale[0];
    int d0 = threadIdx.x * 4;
    float4 o;
    float* op = &o.x;
#pragma unroll
    for (int j = 0; j < 4; j++) {
        const float* w = projw + (size_t)(d0 + j) * 16;
        float acc = 0.f;
#pragma unroll
        for (int k = 0; k < 16; k++) acc = fmaf(f[k], w[k], acc);
        op[j] = acc * es;
    }
    *(float4*)(x + (size_t)bl * D_ + d0) = o;
}

// ---------------- depthwise conv (K=5) -> planes ----------------
__global__ __launch_bounds__(256) void k_dwconv(
    const float* __restrict__ x, const float* __restrict__ w,
    const float* __restrict__ bias, bf16* __restrict__ yh, bf16* __restrict__ yl)
{
    int idx = blockIdx.x * blockDim.x + threadIdx.x;
    int d = idx & (D_ - 1);
    int l = (idx >> 10) & (L_ - 1);
    int b = idx >> 21;
    float acc = bias[d];
#pragma unroll
    for (int k = 0; k < 5; k++) {
        int ll = l + k - 2;
        if (ll >= 0 && ll < L_)
            acc = fmaf(x[((size_t)b * L_ + ll) * D_ + d], w[d * 5 + k], acc);
    }
    bf16 h, lo;
    split1(acc, h, lo);
    yh[idx] = h; yl[idx] = lo;
}

// ---------------- GLU + residual + LayerNorm -> fp32 x + planes ----------------
__global__ __launch_bounds__(256) void k_glu_ln(
    const float* __restrict__ x, const float* __restrict__ y2,
    const float* __restrict__ gbias, const float* __restrict__ lng,
    const float* __restrict__ lnb, float* __restrict__ out,
    bf16* __restrict__ oh, bf16* __restrict__ ol)
{
    __shared__ float redA[8], redB[8];
    int bl = blockIdx.x;
    int tid = threadIdx.x;
    int c = tid * 4;
    const float* xr = x + (size_t)bl * D_;
    const float* yr = y2 + (size_t)bl * 2 * D_;
    float4 xv = *(const float4*)(xr + c);
    float4 sv = *(const float4*)(yr + c);
    float4 gv = *(const float4*)(yr + D_ + c);
    float4 gb = *(const float4*)(gbias + c);
    float t0 = xv.x + sv.x * (1.f / (1.f + __expf(-(gv.x + gb.x))));
    float t1 = xv.y + sv.y * (1.f / (1.f + __expf(-(gv.y + gb.y))));
    float t2 = xv.z + sv.z * (1.f / (1.f + __expf(-(gv.z + gb.z))));
    float t3 = xv.w + sv.w * (1.f / (1.f + __expf(-(gv.w + gb.w))));

    float m = blk_sum(t0 + t1 + t2 + t3, tid, redA) * (1.f / 1024.f);
    float d0 = t0 - m, d1 = t1 - m, d2 = t2 - m, d3 = t3 - m;
    float var = blk_sum(d0 * d0 + d1 * d1 + d2 * d2 + d3 * d3, tid, redB);
    float inv = rsqrtf(var * (1.f / 1024.f) + 1e-5f);
    float4 gg = *(const float4*)(lng + c);
    float4 bb = *(const float4*)(lnb + c);
    float4 o4;
    o4.x = d0 * inv * gg.x + bb.x;
    o4.y = d1 * inv * gg.y + bb.y;
    o4.z = d2 * inv * gg.z + bb.z;
    o4.w = d3 * inv * gg.w + bb.w;
    size_t off = (size_t)bl * D_ + c;
    *(float4*)(out + off) = o4;
    uint32_t h0, l0, h1, l1;
    split2(o4.x, o4.y, h0, l0);
    split2(o4.z, o4.w, h1, l1);
    *(uint2*)(oh + off) = make_uint2(h0, h1);
    *(uint2*)(ol + off) = make_uint2(l0, l1);
}

// ---------------- residual add + LayerNorm ----------------
__global__ __launch_bounds__(256) void k_add_ln(
    const float* __restrict__ x, const float* __restrict__ zv,
    const float* __restrict__ lng, const float* __restrict__ lnb,
    float* __restrict__ out)
{
    __shared__ float redA[8], redB[8];
    int bl = blockIdx.x;
    int tid = threadIdx.x;
    int c = tid * 4;
    float4 xv = *(const float4*)(x + (size_t)bl * D_ + c);
    float4 zz = *(const float4*)(zv + (size_t)bl * D_ + c);
    float t0 = xv.x + zz.x, t1 = xv.y + zz.y, t2 = xv.z + zz.z, t3 = xv.w + zz.w;

    float m = blk_sum(t0 + t1 + t2 + t3, tid, redA) * (1.f / 1024.f);
    float d0 = t0 - m, d1 = t1 - m, d2 = t2 - m, d3 = t3 - m;
    float var = blk_sum(d0 * d0 + d1 * d1 + d2 * d2 + d3 * d3, tid, redB);
    float inv = rsqrtf(var * (1.f / 1024.f) + 1e-5f);
    float4 gg = *(const float4*)(lng + c);
    float4 bb = *(const float4*)(lnb + c);
    float4 o4;
    o4.x = d0 * inv * gg.x + bb.x;
    o4.y = d1 * inv * gg.y + bb.y;
    o4.z = d2 * inv * gg.z + bb.z;
    o4.w = d3 * inv * gg.w + bb.w;
    *(float4*)(out + (size_t)bl * D_ + c) = o4;
}

// ---------------- fused KV pack: K copy + V transpose (one pass) ----------------
__global__ __launch_bounds__(256) void k_pack2(
    const bf16* __restrict__ kvh, const bf16* __restrict__ kvl,
    bf16* __restrict__ kph, bf16* __restrict__ kpl,
    bf16* __restrict__ vth, bf16* __restrict__ vtl)
{
    __shared__ uint16_t th[64][66], tl[64][66];
    const int lt = blockIdx.x;
    const int h16 = blockIdx.y;
    const int b = blockIdx.z;
    const int l0 = lt * 64;
    const int tid = threadIdx.x;
    const int dcol = tid & 63;
    const int r4 = tid >> 6;
    const int G = h16 >> 3, h = h16 & 7;

#pragma unroll
    for (int i = 0; i < 16; i++) {
        int row = i * 4 + r4;
        size_t srow = ((size_t)b * L_ + l0 + row) * 3072 + 1024 + h16 * 128;
        size_t ko = (((size_t)(b * 2 + G) * L_ + l0 + row) * 512) + h * 64 + dcol;
        kph[ko] = kvh[srow + dcol];
        kpl[ko] = kvl[srow + dcol];
        th[row][dcol] = *(const uint16_t*)(kvh + srow + 64 + dcol);
        tl[row][dcol] = *(const uint16_t*)(kvl + srow + 64 + dcol);
    }
    __syncthreads();
#pragma unroll
    for (int i = 0; i < 16; i++) {
        int dim = i * 4 + r4;
        size_t o = ((size_t)b * 512 + h * 64 + dim) * 4096 + (size_t)G * 2048 + l0 + dcol;
        *(uint16_t*)(vth + o) = th[dcol][dim];
        *(uint16_t*)(vtl + o) = tl[dcol][dim];
    }
}

// ---------------- row softmax: stats + exp + split -> P planes ----------------
__global__ __launch_bounds__(256) void k_rowsoft(
    const float* __restrict__ S, bf16* __restrict__ Ph, bf16* __restrict__ Pl)
{
    __shared__ float redA[8], redB[8];
    const int l = blockIdx.x, G = blockIdx.y, bg = blockIdx.z;
    const size_t roff = ((size_t)bg * L_ + l) * 4096 + (size_t)G * 2048;
    const int tid = threadIdx.x;
    float v[8];
    *(float4*)(v)     = *(const float4*)(S + roff + tid * 8);
    *(float4*)(v + 4) = *(const float4*)(S + roff + tid * 8 + 4);
    float m = v[0];
#pragma unroll
    for (int j = 1; j < 8; j++) m = fmaxf(m, v[j]);
    m = blk_max(m, tid, redA);
    float e[8];
    float s = 0.f;
#pragma unroll
    for (int j = 0; j < 8; j++) { e[j] = __expf(v[j] - m); s += e[j]; }
    s = blk_sum(s, tid, redB);
    float inv = 1.f / s;
    uint4 ho, lo4;
    split2(e[0] * inv, e[1] * inv, ho.x, lo4.x);
    split2(e[2] * inv, e[3] * inv, ho.y, lo4.y);
    split2(e[4] * inv, e[5] * inv, ho.z, lo4.z);
    split2(e[6] * inv, e[7] * inv, ho.w, lo4.w);
    *(uint4*)(Ph + roff + tid * 8) = ho;
    *(uint4*)(Pl + roff + tid * 8) = lo4;
}

// ---------------- host ----------------
static void fill1(Batch8& bt)
{
    for (int z = 0; z < 8; z++) {
        bt.offA[z] = bt.offB[z] = bt.offC[z] = 0;
        bt.alpha[z] = 1.f;
    }
}

extern "C" void kernel_launch(void* const* d_in, const int* in_sizes, int n_in,
                              void* d_out, int out_size)
{
    (void)in_sizes; (void)n_in; (void)out_size;
    const int*   tok    = (const int*)  d_in[0];
    const float* ctab   = (const float*)d_in[1];
    const float* projw  = (const float*)d_in[2];
    const float* escale = (const float*)d_in[3];
    const float* dww    = (const float*)d_in[4];
    const float* dwb    = (const float*)d_in[5];
    const float* pww    = (const float*)d_in[6];
    const float* pwb    = (const float*)d_in[7];
    const float* gbias  = (const float*)d_in[8];
    const float* clng   = (const float*)d_in[9];
    const float* clnb   = (const float*)d_in[10];
    const float* qw     = (const float*)d_in[11];
    const float* kvw    = (const float*)d_in[12];
    const float* ow     = (const float*)d_in[13];
    const float* alng   = (const float*)d_in[14];
    const float* alnb   = (const float*)d_in[15];

    cudaFuncSetAttribute(gemm_pp, cudaFuncAttributeMaxDynamicSharedMemorySize, GEMM_SMEM);

    float *x, *t2, *q, *S;
    cudaGetSymbolAddress((void**)&x,  g_x);
    cudaGetSymbolAddress((void**)&t2, g_t2);
    cudaGetSymbolAddress((void**)&q,  g_q);
    cudaGetSymbolAddress((void**)&S,  g_s);
    bf16 *t1h, *t1l, *xh, *xl, *qkvh, *qkvl, *kph, *kpl, *vth, *vtl, *Ph, *Pl, *Wh, *Wl;
    cudaGetSymbolAddress((void**)&t1h, p_t1h);   cudaGetSymbolAddress((void**)&t1l, p_t1l);
    cudaGetSymbolAddress((void**)&xh,  p_xh);    cudaGetSymbolAddress((void**)&xl,  p_xl);
    cudaGetSymbolAddress((void**)&qkvh, p_qkvh); cudaGetSymbolAddress((void**)&qkvl, p_qkvl);
    cudaGetSymbolAddress((void**)&kph, p_kph);   cudaGetSymbolAddress((void**)&kpl, p_kpl);
    cudaGetSymbolAddress((void**)&vth, p_vth);   cudaGetSymbolAddress((void**)&vtl, p_vtl);
    cudaGetSymbolAddress((void**)&Ph,  p_Ph);    cudaGetSymbolAddress((void**)&Pl,  p_Pl);
    cudaGetSymbolAddress((void**)&Wh,  p_Wh);    cudaGetSymbolAddress((void**)&Wl,  p_Wl);

    // weight plane layout: pw_i @ i*2097152 | qkv_i @ 4194304 + i*3145728 | ow_i @ 10485760 + i*1048576
    k_splitall<<<12288, 256>>>(pww, qw, kvw, ow, Wh, Wl);

    k_embed<<<B_ * L_, 256>>>(tok, ctab, projw, escale, x);

    for (int i = 0; i < 2; i++) {
        // --- conv block ---
        k_dwconv<<<(B_ * L_ * D_) / 256, 256>>>(x, dww + (size_t)i * D_ * 5, dwb + i * D_,
                                                t1h, t1l);

        Batch8 b1; fill1(b1);
        gemm_pp<<<dim3(8, 32, 1), 512, GEMM_SMEM>>>(
            t1h, t1l, Wh + (long long)i * 2097152, Wl + (long long)i * 2097152,
            t2, nullptr, nullptr, pwb + i * 2048, 1024, 1024, 1024, 2048, b1);

        k_glu_ln<<<B_ * L_, 256>>>(x, t2, gbias + i * D_, clng + i * D_, clnb + i * D_,
                                   x, xh, xl);

        // --- attention block ---
        const long long OQKV = 4194304 + (long long)i * 3145728;
        gemm_pp<<<dim3(12, 32, 1), 512, GEMM_SMEM>>>(
            xh, xl, Wh + OQKV, Wl + OQKV,
            nullptr, qkvh, qkvl, nullptr, 1024, 1024, 1024, 3072, b1);

        k_pack2<<<dim3(32, 16, 2), 256>>>(qkvh, qkvl, kph, kpl, vth, vtl);

        Batch8 bs; fill1(bs);
        for (int zz = 0; zz < 8; zz++) {
            int bg = zz >> 1, G = zz & 1;
            int b = bg >> 1, g = bg & 1;
            bs.offA[zz] = (long long)b * L_ * 3072 + g * 512;
            bs.offB[zz] = (long long)(b * 2 + G) * L_ * 512;
            bs.offC[zz] = (long long)bg * L_ * 4096 + G * 2048;
            bs.alpha[zz] = 0.125f * (G ? 2.0f : 1.0f);
        }
        gemm_pp<<<dim3(8, 16, 8), 512, GEMM_SMEM>>>(
            qkvh, qkvl, kph, kpl, S, nullptr, nullptr, nullptr, 512, 3072, 512, 4096, bs);

        k_rowsoft<<<dim3(L_, 2, 4), 256>>>(S, Ph, Pl);

        // attention out: split-K=2 over the 4096 contraction -> fp32 partials in g_s
        // z = bg*2 + kh; partial kh at S + kh*4194304, layout [bg][l][dd(512)]
        Batch8 bo; fill1(bo);
        for (int zz = 0; zz < 8; zz++) {
            int bg = zz >> 1, kh = zz & 1;
            int b = bg >> 1;
            bo.offA[zz] = (long long)bg * L_ * 4096 + kh * 2048;
            bo.offB[zz] = (long long)b * 512 * 4096 + kh * 2048;
            bo.offC[zz] = (long long)kh * 4194304 + (long long)bg * L_ * 512;
        }
        gemm_pp<<<dim3(2, 16, 8), 512, GEMM_SMEM>>>(
            Ph, Pl, vth, vtl, S, nullptr, nullptr, nullptr, 2048, 4096, 4096, 512, bo);

        k_combine<<<4096, 256>>>(S, t1h, t1l);

        const long long OOW = 10485760 + (long long)i * 1048576;
        gemm_pp<<<dim3(4, 32, 1), 512, GEMM_SMEM>>>(
            t1h, t1l, Wh + OOW, Wl + OOW,
            q, nullptr, nullptr, nullptr, 1024, 1024, 1024, 1024, b1);

        float* dst = (i == 1) ? (float*)d_out : x;
        k_add_ln<<<B_ * L_, 256>>>(x, q, alng + i * D_, alnb + i * D_, dst);
    }
}

// round 15
// speedup vs baseline: 1.0147x; 1.0147x over previous
#include <cuda_runtime.h>
#include <cuda_bf16.h>
#include <math.h>
#include <stdint.h>

#define D_ 1024
#define L_ 2048
#define B_ 2

typedef __nv_bfloat16 bf16;

// GEMM: CTA 128x256, 512 thr, warps 4M x 4N (32x64 each), KC=64, 2-stage cp.async
#define STG_BYTES 98304
#define GEMM_SMEM (2 * STG_BYTES + 1024)

// ---------------- fp32 scratch ----------------
__device__ float g_x [B_ * L_ * D_];
__device__ float g_t2[B_ * L_ * 2 * D_];
__device__ float g_q [B_ * L_ * D_];
__device__ float g_s [4LL * L_ * 4096];

// ---------------- bf16 hi/lo planes ----------------
__device__ __align__(16) bf16 p_t1h [B_ * L_ * D_],       p_t1l [B_ * L_ * D_];
__device__ __align__(16) bf16 p_xh  [B_ * L_ * D_],       p_xl  [B_ * L_ * D_];
__device__ __align__(16) bf16 p_qkvh[B_ * L_ * 3072],     p_qkvl[B_ * L_ * 3072];
__device__ __align__(16) bf16 p_kph [B_ * 2 * L_ * 512],  p_kpl [B_ * 2 * L_ * 512];
__device__ __align__(16) bf16 p_vth [B_ * 512 * 2 * L_],  p_vtl [B_ * 512 * 2 * L_];
__device__ __align__(16) bf16 p_Ph  [4LL * L_ * 4096],    p_Pl  [4LL * L_ * 4096];
__device__ __align__(16) bf16 p_Wh  [12 * 1024 * 1024],   p_Wl  [12 * 1024 * 1024];

struct Batch8 {
    long long offA[8];
    long long offB[8];
    long long offC[8];
    float alpha[8];
};

// ---------------- helpers ----------------
__device__ __forceinline__ uint32_t smem_u32(const void* p) {
    uint32_t a;
    asm("{ .reg .u64 t; cvta.to.shared.u64 t, %1; cvt.u32.u64 %0, t; }" : "=r"(a) : "l"(p));
    return a;
}
__device__ __forceinline__ void split2(float a, float b, uint32_t& hi, uint32_t& lo) {
    uint32_t h;
    asm("cvt.rn.satfinite.bf16x2.f32 %0, %1, %2;" : "=r"(h) : "f"(b), "f"(a));
    float ra = a - __uint_as_float(h << 16);
    float rb = b - __uint_as_float(h & 0xffff0000u);
    uint32_t l;
    asm("cvt.rn.satfinite.bf16x2.f32 %0, %1, %2;" : "=r"(l) : "f"(rb), "f"(ra));
    hi = h; lo = l;
}
__device__ __forceinline__ void split1(float a, bf16& h, bf16& l) {
    h = __float2bfloat16_rn(a);
    l = __float2bfloat16_rn(a - __bfloat162float(h));
}
// non-volatile: lets ptxas interleave HMMAs with LDSMs
__device__ __forceinline__ void mma_bf16(float* c, const uint32_t* a, uint32_t b0, uint32_t b1) {
    asm("mma.sync.aligned.m16n8k16.row.col.f32.bf16.bf16.f32 "
        "{%0,%1,%2,%3}, {%4,%5,%6,%7}, {%8,%9}, {%0,%1,%2,%3};"
        : "+f"(c[0]), "+f"(c[1]), "+f"(c[2]), "+f"(c[3])
        : "r"(a[0]), "r"(a[1]), "r"(a[2]), "r"(a[3]), "r"(b0), "r"(b1));
}
__device__ __forceinline__ void cpa16(uint32_t s, const bf16* g) {
    asm volatile("cp.async.cg.shared.global [%0], [%1], 16;"
                 :: "r"(s), "l"(__cvta_generic_to_global((const void*)g)) : "memory");
}
__device__ __forceinline__ void ldm4(uint32_t addr, uint32_t* r) {
    asm volatile("ldmatrix.sync.aligned.m8n8.x4.shared.b16 {%0,%1,%2,%3}, [%4];"
                 : "=r"(r[0]), "=r"(r[1]), "=r"(r[2]), "=r"(r[3]) : "r"(addr));
}

// block reductions for 256 threads: 1 barrier each (disjoint 8-word buffers)
__device__ __forceinline__ float blk_sum(float v, int tid, volatile float* red8) {
#pragma unroll
    for (int o = 16; o > 0; o >>= 1) v += __shfl_xor_sync(0xffffffffu, v, o);
    if ((tid & 31) == 0) red8[tid >> 5] = v;
    __syncthreads();
    float s = red8[tid & 7];
#pragma unroll
    for (int o = 4; o > 0; o >>= 1) s += __shfl_xor_sync(0xffffffffu, s, o);
    return s;
}
__device__ __forceinline__ float blk_max(float v, int tid, volatile float* red8) {
#pragma unroll
    for (int o = 16; o > 0; o >>= 1) v = fmaxf(v, __shfl_xor_sync(0xffffffffu, v, o));
    if ((tid & 31) == 0) red8[tid >> 5] = v;
    __syncthreads();
    float s = red8[tid & 7];
#pragma unroll
    for (int o = 4; o > 0; o >>= 1) s = fmaxf(s, __shfl_xor_sync(0xffffffffu, s, o));
    return s;
}

// ---------------- plane-operand GEMM: C = alpha * A(MxK) * B(NxK)^T ----------------
// Round-9 mainloop (verified optimum): single barrier per K-chunk.
__global__ __launch_bounds__(512, 1) void gemm_pp(
    const bf16* __restrict__ Ah, const bf16* __restrict__ Al,
    const bf16* __restrict__ Bh, const bf16* __restrict__ Bl,
    float* __restrict__ C, bf16* __restrict__ Ch, bf16* __restrict__ Cl,
    const float* __restrict__ bias,
    int K, int lda, int ldb, int ldc, Batch8 bt)
{
    extern __shared__ char dsm[];
    uint32_t base = smem_u32(dsm);
    base = (base + 1023u) & ~1023u;

    const int z = blockIdx.z;
    const bf16* gAh = Ah + bt.offA[z];
    const bf16* gAl = Al + bt.offA[z];
    const bf16* gBh = Bh + bt.offB[z];
    const bf16* gBl = Bl + bt.offB[z];
    const float alpha = bt.alpha[z];

    const int tid = threadIdx.x;
    const int lane = tid & 31;
    const int wid = tid >> 5;
    const int wm = wid >> 2, wn = wid & 3;
    const int bm = blockIdx.y * 128, bn = blockIdx.x * 256;

    // cp.async: per thread 4 A chunks (rows rowT+{0,32,64,96}) + 8 B chunks (+{0..224})
    const int rowT = tid >> 4;
    const int sub  = tid & 15;
    const int plane = sub >> 3;
    const int c4 = sub & 7;
    const bf16* aP = (plane ? gAl : gAh) + (size_t)(bm + rowT) * lda + c4 * 8;
    const bf16* bP = (plane ? gBl : gBh) + (size_t)(bn + rowT) * ldb + c4 * 8;
    const uint32_t swz = ((uint32_t)c4 * 16u) ^ (((uint32_t)rowT & 7u) << 4);
    const uint32_t sA = base + (uint32_t)rowT * 256u + (uint32_t)plane * 128u + swz;
    const uint32_t sB = base + 32768u + (uint32_t)rowT * 256u + (uint32_t)plane * 128u + swz;
    const size_t stepA = (size_t)32 * lda;
    const size_t stepB = (size_t)32 * ldb;

    // fragment addressing
    const int rA = lane & 15, khA = lane >> 4;
    const uint32_t abase = base + (uint32_t)(wm * 32 + rA) * 256u;
    const uint32_t swA = ((uint32_t)rA & 7u) << 4;
    const int rBr = (lane & 7) + ((lane >> 4) << 3);
    const int khB = (lane >> 3) & 1;
    const uint32_t bbase = base + 32768u + (uint32_t)(wn * 64 + rBr) * 256u;
    const uint32_t swB = ((uint32_t)rBr & 7u) << 4;

    float acc[2][8][4];
#pragma unroll
    for (int i = 0; i < 2; i++)
#pragma unroll
        for (int j = 0; j < 8; j++)
#pragma unroll
            for (int c = 0; c < 4; c++) acc[i][j][c] = 0.f;

    const int nk = K >> 6;

    // prologue: stage 0
#pragma unroll
    for (int i = 0; i < 4; i++) cpa16(sA + i * 8192u, aP + (size_t)i * stepA);
#pragma unroll
    for (int i = 0; i < 8; i++) cpa16(sB + i * 8192u, bP + (size_t)i * stepB);
    asm volatile("cp.async.commit_group;" ::: "memory");

    for (int kt = 0; kt < nk; kt++) {
        asm volatile("cp.async.wait_group 0;" ::: "memory");
        __syncthreads();
        if (kt + 1 < nk) {
            const uint32_t so2 = ((kt + 1) & 1) * (uint32_t)STG_BYTES;
            const int k0 = (kt + 1) << 6;
#pragma unroll
            for (int i = 0; i < 4; i++) cpa16(sA + so2 + i * 8192u, aP + k0 + (size_t)i * stepA);
#pragma unroll
            for (int i = 0; i < 8; i++) cpa16(sB + so2 + i * 8192u, bP + k0 + (size_t)i * stepB);
            asm volatile("cp.async.commit_group;" ::: "memory");
        }
        const uint32_t so = (kt & 1) * (uint32_t)STG_BYTES;
        const uint32_t ab = abase + so;
        const uint32_t bb = bbase + so;
#pragma unroll
        for (int s = 0; s < 4; s++) {
            const uint32_t aoff = ((uint32_t)((s * 2 + khA) * 16)) ^ swA;
            const uint32_t boff = ((uint32_t)((s * 2 + khB) * 16)) ^ swB;
            uint32_t ah[2][4], al[2][4];
#pragma unroll
            for (int mb = 0; mb < 2; mb++) {
                ldm4(ab + mb * 4096 + aoff, ah[mb]);
                ldm4(ab + mb * 4096 + 128 + aoff, al[mb]);
            }
#pragma unroll
            for (int half = 0; half < 2; half++) {
                uint32_t bh[2][4], bl[2][4];
#pragma unroll
                for (int p2 = 0; p2 < 2; p2++) {
                    const int pr = half * 2 + p2;
                    ldm4(bb + pr * 4096 + boff, bh[p2]);
                    ldm4(bb + pr * 4096 + 128 + boff, bl[p2]);
                }
                // P1: Ah x Bh (8 MMAs, distinct accumulators)
#pragma unroll
                for (int p2 = 0; p2 < 2; p2++)
#pragma unroll
                    for (int nb2 = 0; nb2 < 2; nb2++)
#pragma unroll
                        for (int mb = 0; mb < 2; mb++)
                            mma_bf16(acc[mb][(half * 2 + p2) * 2 + nb2],
                                     ah[mb], bh[p2][nb2 * 2], bh[p2][nb2 * 2 + 1]);
                // P2: Ah x Bl
#pragma unroll
                for (int p2 = 0; p2 < 2; p2++)
#pragma unroll
                    for (int nb2 = 0; nb2 < 2; nb2++)
#pragma unroll
                        for (int mb = 0; mb < 2; mb++)
                            mma_bf16(acc[mb][(half * 2 + p2) * 2 + nb2],
                                     ah[mb], bl[p2][nb2 * 2], bl[p2][nb2 * 2 + 1]);
                // P3: Al x Bh
#pragma unroll
                for (int p2 = 0; p2 < 2; p2++)
#pragma unroll
                    for (int nb2 = 0; nb2 < 2; nb2++)
#pragma unroll
                        for (int mb = 0; mb < 2; mb++)
                            mma_bf16(acc[mb][(half * 2 + p2) * 2 + nb2],
                                     al[mb], bh[p2][nb2 * 2], bh[p2][nb2 * 2 + 1]);
            }
        }
    }

    // ---- epilogue ----
    const int qr = lane >> 2, qc = lane & 3;
    if (Ch) {
#pragma unroll
        for (int mb = 0; mb < 2; mb++) {
            const int row = bm + wm * 32 + mb * 16 + qr;
#pragma unroll
            for (int nb = 0; nb < 8; nb++) {
                const int col = bn + wn * 64 + nb * 8 + qc * 2;
                uint32_t h0, l0, h1, l1;
                split2(acc[mb][nb][0] * alpha, acc[mb][nb][1] * alpha, h0, l0);
                split2(acc[mb][nb][2] * alpha, acc[mb][nb][3] * alpha, h1, l1);
                const long long o0 = bt.offC[z] + (long long)row * ldc + col;
                const long long o1 = bt.offC[z] + (long long)(row + 8) * ldc + col;
                *(uint32_t*)(Ch + o0) = h0; *(uint32_t*)(Cl + o0) = l0;
                *(uint32_t*)(Ch + o1) = h1; *(uint32_t*)(Cl + o1) = l1;
            }
        }
    } else {
        float* Cz = C + bt.offC[z];
#pragma unroll
        for (int mb = 0; mb < 2; mb++) {
            const int row = bm + wm * 32 + mb * 16 + qr;
#pragma unroll
            for (int nb = 0; nb < 8; nb++) {
                const int col = bn + wn * 64 + nb * 8 + qc * 2;
                float2 v0, v1;
                v0.x = acc[mb][nb][0] * alpha;
                v0.y = acc[mb][nb][1] * alpha;
                v1.x = acc[mb][nb][2] * alpha;
                v1.y = acc[mb][nb][3] * alpha;
                if (bias) {
                    float2 bv = *(const float2*)(bias + col);
                    v0.x += bv.x; v0.y += bv.y;
                    v1.x += bv.x; v1.y += bv.y;
                }
                *(float2*)(Cz + (size_t)row * ldc + col) = v0;
                *(float2*)(Cz + (size_t)(row + 8) * ldc + col) = v1;
            }
        }
    }
}

// ---------------- weight split, layout: pw0|pw1 | (q0,kv0)|(q1,kv1) | ow0|ow1 ----------------
__global__ __launch_bounds__(256) void k_splitall(
    const float* __restrict__ pww, const float* __restrict__ qw,
    const float* __restrict__ kvw, const float* __restrict__ ow,
    bf16* __restrict__ h, bf16* __restrict__ l)
{
    long long i = (long long)blockIdx.x * 256 + threadIdx.x;
    const float* src;
    long long s;
    if (i < 1048576) { src = pww; s = i; }
    else if (i < 2621440) {
        long long j = i - 1048576;
        int layer = (int)(j / 786432);
        long long r = j - (long long)layer * 786432;
        if (r < 262144) { src = qw;  s = (long long)layer * 262144 + r; }
        else            { src = kvw; s = (long long)layer * 524288 + (r - 262144); }
    }
    else { src = ow; s = i - 2621440; }
    float4 v = ((const float4*)src)[s];
    uint32_t h0, l0, h1, l1;
    split2(v.x, v.y, h0, l0);
    split2(v.z, v.w, h1, l1);
    ((uint2*)h)[i] = make_uint2(h0, h1);
    ((uint2*)l)[i] = make_uint2(l0, l1);
}

// ---------------- Julia embedding ----------------
__global__ __launch_bounds__(256) void k_embed(
    const int* __restrict__ tok, const float* __restrict__ ctab,
    const float* __restrict__ projw, const float* __restrict__ escale,
    float* __restrict__ x)
{
    int bl = blockIdx.x;
    int t = tok[bl];
    float cr = ctab[2 * t], ci = ctab[2 * t + 1];
    float f[16];
    float zr = 0.f, zi = 0.f;
#pragma unroll
    for (int s = 0; s < 8; s++) {
        float nr = zr * zr - zi * zi + cr;
        float ni = 2.f * zr * zi + ci;
        zr = nr; zi = ni;
        f[2 * s] = zr; f[2 * s + 1] = zi;
    }
    float es = escale[0];
    int d0 = threadIdx.x * 4;
    float4 o;
    float* op = &o.x;
#pragma unroll
    for (int j = 0; j < 4; j++) {
        const float* w = projw + (size_t)(d0 + j) * 16;
        float acc = 0.f;
#pragma unroll
        for (int k = 0; k < 16; k++) acc = fmaf(f[k], w[k], acc);
        op[j] = acc * es;
    }
    *(float4*)(x + (size_t)bl * D_ + d0) = o;
}

// ---------------- depthwise conv (K=5), smem-tiled along l -> planes ----------------
// block: (b, l-tile of 32, d-chunk of 256). smem stages rows l0-2 .. l0+33.
__global__ __launch_bounds__(256) void k_dwconv(
    const float* __restrict__ x, const float* __restrict__ w,
    const float* __restrict__ bias, bf16* __restrict__ yh, bf16* __restrict__ yl)
{
    __shared__ float sx[36][256];
    const int lt = blockIdx.x;          // 0..63  (l-tile)
    const int dc = blockIdx.y;          // 0..3   (d-chunk)
    const int b  = blockIdx.z;          // 0..1
    const int tid = threadIdx.x;
    const int l0 = lt * 32;
    const int d  = dc * 256 + tid;

    const float* xb = x + (size_t)b * L_ * D_ + d;
#pragma unroll
    for (int i = 0; i < 36; i++) {
        int ll = l0 - 2 + i;
        sx[i][tid] = (ll >= 0 && ll < L_) ? xb[(size_t)ll * D_] : 0.f;
    }
    __syncthreads();

    const float bsv = bias[d];
    float w0 = w[d * 5 + 0], w1 = w[d * 5 + 1], w2 = w[d * 5 + 2],
          w3 = w[d * 5 + 3], w4 = w[d * 5 + 4];
    bf16* oyh = yh + ((size_t)b * L_ + l0) * D_ + d;
    bf16* oyl = yl + ((size_t)b * L_ + l0) * D_ + d;
#pragma unroll
    for (int j = 0; j < 32; j++) {
        float acc = bsv;
        acc = fmaf(sx[j + 0][tid], w0, acc);
        acc = fmaf(sx[j + 1][tid], w1, acc);
        acc = fmaf(sx[j + 2][tid], w2, acc);
        acc = fmaf(sx[j + 3][tid], w3, acc);
        acc = fmaf(sx[j + 4][tid], w4, acc);
        bf16 h, lo;
        split1(acc, h, lo);
        oyh[(size_t)j * D_] = h;
        oyl[(size_t)j * D_] = lo;
    }
}

// ---------------- GLU + residual + LayerNorm -> fp32 x + planes ----------------
__global__ __launch_bounds__(256) void k_glu_ln(
    const float* __restrict__ x, const float* __restrict__ y2,
    const float* __restrict__ gbias, const float* __restrict__ lng,
    const float* __restrict__ lnb, float* __restrict__ out,
    bf16* __restrict__ oh, bf16* __restrict__ ol)
{
    __shared__ float redA[8], redB[8];
    int bl = blockIdx.x;
    int tid = threadIdx.x;
    int c = tid * 4;
    const float* xr = x + (size_t)bl * D_;
    const float* yr = y2 + (size_t)bl * 2 * D_;
    float4 xv = *(const float4*)(xr + c);
    float4 sv = *(const float4*)(yr + c);
    float4 gv = *(const float4*)(yr + D_ + c);
    float4 gb = *(const float4*)(gbias + c);
    float t0 = xv.x + sv.x * (1.f / (1.f + __expf(-(gv.x + gb.x))));
    float t1 = xv.y + sv.y * (1.f / (1.f + __expf(-(gv.y + gb.y))));
    float t2 = xv.z + sv.z * (1.f / (1.f + __expf(-(gv.z + gb.z))));
    float t3 = xv.w + sv.w * (1.f / (1.f + __expf(-(gv.w + gb.w))));

    float m = blk_sum(t0 + t1 + t2 + t3, tid, redA) * (1.f / 1024.f);
    float d0 = t0 - m, d1 = t1 - m, d2 = t2 - m, d3 = t3 - m;
    float var = blk_sum(d0 * d0 + d1 * d1 + d2 * d2 + d3 * d3, tid, redB);
    float inv = rsqrtf(var * (1.f / 1024.f) + 1e-5f);
    float4 gg = *(const float4*)(lng + c);
    float4 bb = *(const float4*)(lnb + c);
    float4 o4;
    o4.x = d0 * inv * gg.x + bb.x;
    o4.y = d1 * inv * gg.y + bb.y;
    o4.z = d2 * inv * gg.z + bb.z;
    o4.w = d3 * inv * gg.w + bb.w;
    size_t off = (size_t)bl * D_ + c;
    *(float4*)(out + off) = o4;
    uint32_t h0, l0, h1, l1;
    split2(o4.x, o4.y, h0, l0);
    split2(o4.z, o4.w, h1, l1);
    *(uint2*)(oh + off) = make_uint2(h0, h1);
    *(uint2*)(ol + off) = make_uint2(l0, l1);
}

// ---------------- residual add + LayerNorm ----------------
__global__ __launch_bounds__(256) void k_add_ln(
    const float* __restrict__ x, const float* __restrict__ zv,
    const float* __restrict__ lng, const float* __restrict__ lnb,
    float* __restrict__ out)
{
    __shared__ float redA[8], redB[8];
    int bl = blockIdx.x;
    int tid = threadIdx.x;
    int c = tid * 4;
    float4 xv = *(const float4*)(x + (size_t)bl * D_ + c);
    float4 zz = *(const float4*)(zv + (size_t)bl * D_ + c);
    float t0 = xv.x + zz.x, t1 = xv.y + zz.y, t2 = xv.z + zz.z, t3 = xv.w + zz.w;

    float m = blk_sum(t0 + t1 + t2 + t3, tid, redA) * (1.f / 1024.f);
    float d0 = t0 - m, d1 = t1 - m, d2 = t2 - m, d3 = t3 - m;
    float var = blk_sum(d0 * d0 + d1 * d1 + d2 * d2 + d3 * d3, tid, redB);
    float inv = rsqrtf(var * (1.f / 1024.f) + 1e-5f);
    float4 gg = *(const float4*)(lng + c);
    float4 bb = *(const float4*)(lnb + c);
    float4 o4;
    o4.x = d0 * inv * gg.x + bb.x;
    o4.y = d1 * inv * gg.y + bb.y;
    o4.z = d2 * inv * gg.z + bb.z;
    o4.w = d3 * inv * gg.w + bb.w;
    *(float4*)(out + (size_t)bl * D_ + c) = o4;
}

// ---------------- fused KV pack: K copy + V transpose (one pass) ----------------
__global__ __launch_bounds__(256) void k_pack2(
    const bf16* __restrict__ kvh, const bf16* __restrict__ kvl,
    bf16* __restrict__ kph, bf16* __restrict__ kpl,
    bf16* __restrict__ vth, bf16* __restrict__ vtl)
{
    __shared__ uint16_t th[64][66], tl[64][66];
    const int lt = blockIdx.x;
    const int h16 = blockIdx.y;
    const int b = blockIdx.z;
    const int l0 = lt * 64;
    const int tid = threadIdx.x;
    const int dcol = tid & 63;
    const int r4 = tid >> 6;
    const int G = h16 >> 3, h = h16 & 7;

#pragma unroll
    for (int i = 0; i < 16; i++) {
        int row = i * 4 + r4;
        size_t srow = ((size_t)b * L_ + l0 + row) * 3072 + 1024 + h16 * 128;
        size_t ko = (((size_t)(b * 2 + G) * L_ + l0 + row) * 512) + h * 64 + dcol;
        kph[ko] = kvh[srow + dcol];
        kpl[ko] = kvl[srow + dcol];
        th[row][dcol] = *(const uint16_t*)(kvh + srow + 64 + dcol);
        tl[row][dcol] = *(const uint16_t*)(kvl + srow + 64 + dcol);
    }
    __syncthreads();
#pragma unroll
    for (int i = 0; i < 16; i++) {
        int dim = i * 4 + r4;
        size_t o = ((size_t)b * 512 + h * 64 + dim) * 4096 + (size_t)G * 2048 + l0 + dcol;
        *(uint16_t*)(vth + o) = th[dcol][dim];
        *(uint16_t*)(vtl + o) = tl[dcol][dim];
    }
}

// ---------------- row softmax: stats + exp + split -> P planes ----------------
__global__ __launch_bounds__(256) void k_rowsoft(
    const float* __restrict__ S, bf16* __restrict__ Ph, bf16* __restrict__ Pl)
{
    __shared__ float redA[8], redB[8];
    const int l = blockIdx.x, G = blockIdx.y, bg = blockIdx.z;
    const size_t roff = ((size_t)bg * L_ + l) * 4096 + (size_t)G * 2048;
    const int tid = threadIdx.x;
    float v[8];
    *(float4*)(v)     = *(const float4*)(S + roff + tid * 8);
    *(float4*)(v + 4) = *(const float4*)(S + roff + tid * 8 + 4);
    float m = v[0];
#pragma unroll
    for (int j = 1; j < 8; j++) m = fmaxf(m, v[j]);
    m = blk_max(m, tid, redA);
    float e[8];
    float s = 0.f;
#pragma unroll
    for (int j = 0; j < 8; j++) { e[j] = __expf(v[j] - m); s += e[j]; }
    s = blk_sum(s, tid, redB);
    float inv = 1.f / s;
    uint4 ho, lo4;
    split2(e[0] * inv, e[1] * inv, ho.x, lo4.x);
    split2(e[2] * inv, e[3] * inv, ho.y, lo4.y);
    split2(e[4] * inv, e[5] * inv, ho.z, lo4.z);
    split2(e[6] * inv, e[7] * inv, ho.w, lo4.w);
    *(uint4*)(Ph + roff + tid * 8) = ho;
    *(uint4*)(Pl + roff + tid * 8) = lo4;
}

// ---------------- host ----------------
static void fill1(Batch8& bt)
{
    for (int z = 0; z < 8; z++) {
        bt.offA[z] = bt.offB[z] = bt.offC[z] = 0;
        bt.alpha[z] = 1.f;
    }
}

extern "C" void kernel_launch(void* const* d_in, const int* in_sizes, int n_in,
                              void* d_out, int out_size)
{
    (void)in_sizes; (void)n_in; (void)out_size;
    const int*   tok    = (const int*)  d_in[0];
    const float* ctab   = (const float*)d_in[1];
    const float* projw  = (const float*)d_in[2];
    const float* escale = (const float*)d_in[3];
    const float* dww    = (const float*)d_in[4];
    const float* dwb    = (const float*)d_in[5];
    const float* pww    = (const float*)d_in[6];
    const float* pwb    = (const float*)d_in[7];
    const float* gbias  = (const float*)d_in[8];
    const float* clng   = (const float*)d_in[9];
    const float* clnb   = (const float*)d_in[10];
    const float* qw     = (const float*)d_in[11];
    const float* kvw    = (const float*)d_in[12];
    const float* ow     = (const float*)d_in[13];
    const float* alng   = (const float*)d_in[14];
    const float* alnb   = (const float*)d_in[15];

    cudaFuncSetAttribute(gemm_pp, cudaFuncAttributeMaxDynamicSharedMemorySize, GEMM_SMEM);

    float *x, *t2, *q, *S;
    cudaGetSymbolAddress((void**)&x,  g_x);
    cudaGetSymbolAddress((void**)&t2, g_t2);
    cudaGetSymbolAddress((void**)&q,  g_q);
    cudaGetSymbolAddress((void**)&S,  g_s);
    bf16 *t1h, *t1l, *xh, *xl, *qkvh, *qkvl, *kph, *kpl, *vth, *vtl, *Ph, *Pl, *Wh, *Wl;
    cudaGetSymbolAddress((void**)&t1h, p_t1h);   cudaGetSymbolAddress((void**)&t1l, p_t1l);
    cudaGetSymbolAddress((void**)&xh,  p_xh);    cudaGetSymbolAddress((void**)&xl,  p_xl);
    cudaGetSymbolAddress((void**)&qkvh, p_qkvh); cudaGetSymbolAddress((void**)&qkvl, p_qkvl);
    cudaGetSymbolAddress((void**)&kph, p_kph);   cudaGetSymbolAddress((void**)&kpl, p_kpl);
    cudaGetSymbolAddress((void**)&vth, p_vth);   cudaGetSymbolAddress((void**)&vtl, p_vtl);
    cudaGetSymbolAddress((void**)&Ph,  p_Ph);    cudaGetSymbolAddress((void**)&Pl,  p_Pl);
    cudaGetSymbolAddress((void**)&Wh,  p_Wh);    cudaGetSymbolAddress((void**)&Wl,  p_Wl);

    // weight plane layout: pw_i @ i*2097152 | qkv_i @ 4194304 + i*3145728 | ow_i @ 10485760 + i*1048576
    k_splitall<<<12288, 256>>>(pww, qw, kvw, ow, Wh, Wl);

    k_embed<<<B_ * L_, 256>>>(tok, ctab, projw, escale, x);

    for (int i = 0; i < 2; i++) {
        // --- conv block ---
        k_dwconv<<<dim3(64, 4, 2), 256>>>(x, dww + (size_t)i * D_ * 5, dwb + i * D_,
                                          t1h, t1l);

        Batch8 b1; fill1(b1);
        gemm_pp<<<dim3(8, 32, 1), 512, GEMM_SMEM>>>(
            t1h, t1l, Wh + (long long)i * 2097152, Wl + (long long)i * 2097152,
            t2, nullptr, nullptr, pwb + i * 2048, 1024, 1024, 1024, 2048, b1);

        k_glu_ln<<<B_ * L_, 256>>>(x, t2, gbias + i * D_, clng + i * D_, clnb + i * D_,
                                   x, xh, xl);

        // --- attention block ---
        const long long OQKV = 4194304 + (long long)i * 3145728;
        gemm_pp<<<dim3(12, 32, 1), 512, GEMM_SMEM>>>(
            xh, xl, Wh + OQKV, Wl + OQKV,
            nullptr, qkvh, qkvl, nullptr, 1024, 1024, 1024, 3072, b1);

        k_pack2<<<dim3(32, 16, 2), 256>>>(qkvh, qkvl, kph, kpl, vth, vtl);

        Batch8 bs; fill1(bs);
        for (int zz = 0; zz < 8; zz++) {
            int bg = zz >> 1, G = zz & 1;
            int b = bg >> 1, g = bg & 1;
            bs.offA[zz] = (long long)b * L_ * 3072 + g * 512;
            bs.offB[zz] = (long long)(b * 2 + G) * L_ * 512;
            bs.offC[zz] = (long long)bg * L_ * 4096 + G * 2048;
            bs.alpha[zz] = 0.125f * (G ? 2.0f : 1.0f);
        }
        gemm_pp<<<dim3(8, 16, 8), 512, GEMM_SMEM>>>(
            qkvh, qkvl, kph, kpl, S, nullptr, nullptr, nullptr, 512, 3072, 512, 4096, bs);

        k_rowsoft<<<dim3(L_, 2, 4), 256>>>(S, Ph, Pl);

        Batch8 bo; fill1(bo);
        for (int zz = 0; zz < 4; zz++) {
            int b = zz >> 1, g = zz & 1;
            bo.offA[zz] = (long long)zz * L_ * 4096;
            bo.offB[zz] = (long long)b * 512 * 4096;
            bo.offC[zz] = (long long)b * L_ * 1024 + g * 512;
        }
        gemm_pp<<<dim3(2, 16, 4), 512, GEMM_SMEM>>>(
            Ph, Pl, vth, vtl, nullptr, t1h, t1l, nullptr, 4096, 4096, 4096, 1024, bo);

        const long long OOW = 10485760 + (long long)i * 1048576;
        gemm_pp<<<dim3(4, 32, 1), 512, GEMM_SMEM>>>(
            t1h, t1l, Wh + OOW, Wl + OOW,
            q, nullptr, nullptr, nullptr, 1024, 1024, 1024, 1024, b1);

        float* dst = (i == 1) ? (float*)d_out : x;
        k_add_ln<<<B_ * L_, 256>>>(x, q, alng + i * D_, alnb + i * D_, dst);
    }
}

// round 16
// speedup vs baseline: 1.0231x; 1.0083x over previous
#include <cuda_runtime.h>
#include <cuda_bf16.h>
#include <math.h>
#include <stdint.h>

#define D_ 1024
#define L_ 2048
#define B_ 2

typedef __nv_bfloat16 bf16;

// GEMM: CTA 128x256, 512 thr, warps 4M x 4N (32x64 each), KC=64, 2-stage cp.async
#define STG_BYTES 98304
#define GEMM_SMEM (2 * STG_BYTES + 1024)

// ---------------- fp32 scratch ----------------
__device__ float g_x [B_ * L_ * D_];
__device__ float g_t2[B_ * L_ * 2 * D_];
__device__ float g_q [B_ * L_ * D_];
__device__ float g_s [4LL * L_ * 4096];

// ---------------- bf16 hi/lo planes ----------------
__device__ __align__(16) bf16 p_t1h [B_ * L_ * D_],       p_t1l [B_ * L_ * D_];
__device__ __align__(16) bf16 p_xh  [B_ * L_ * D_],       p_xl  [B_ * L_ * D_];
__device__ __align__(16) bf16 p_qkvh[B_ * L_ * 3072],     p_qkvl[B_ * L_ * 3072];
__device__ __align__(16) bf16 p_vth [B_ * 512 * 2 * L_],  p_vtl [B_ * 512 * 2 * L_];
__device__ __align__(16) bf16 p_Ph  [4LL * L_ * 4096],    p_Pl  [4LL * L_ * 4096];
__device__ __align__(16) bf16 p_Wh  [12 * 1024 * 1024],   p_Wl  [12 * 1024 * 1024];

struct Batch8 {
    long long offA[8];
    long long offB[8];
    long long offC[8];
    float alpha[8];
};

// ---------------- helpers ----------------
__device__ __forceinline__ uint32_t smem_u32(const void* p) {
    uint32_t a;
    asm("{ .reg .u64 t; cvta.to.shared.u64 t, %1; cvt.u32.u64 %0, t; }" : "=r"(a) : "l"(p));
    return a;
}
__device__ __forceinline__ void split2(float a, float b, uint32_t& hi, uint32_t& lo) {
    uint32_t h;
    asm("cvt.rn.satfinite.bf16x2.f32 %0, %1, %2;" : "=r"(h) : "f"(b), "f"(a));
    float ra = a - __uint_as_float(h << 16);
    float rb = b - __uint_as_float(h & 0xffff0000u);
    uint32_t l;
    asm("cvt.rn.satfinite.bf16x2.f32 %0, %1, %2;" : "=r"(l) : "f"(rb), "f"(ra));
    hi = h; lo = l;
}
__device__ __forceinline__ void split1(float a, bf16& h, bf16& l) {
    h = __float2bfloat16_rn(a);
    l = __float2bfloat16_rn(a - __bfloat162float(h));
}
// non-volatile: lets ptxas interleave HMMAs with LDSMs
__device__ __forceinline__ void mma_bf16(float* c, const uint32_t* a, uint32_t b0, uint32_t b1) {
    asm("mma.sync.aligned.m16n8k16.row.col.f32.bf16.bf16.f32 "
        "{%0,%1,%2,%3}, {%4,%5,%6,%7}, {%8,%9}, {%0,%1,%2,%3};"
        : "+f"(c[0]), "+f"(c[1]), "+f"(c[2]), "+f"(c[3])
        : "r"(a[0]), "r"(a[1]), "r"(a[2]), "r"(a[3]), "r"(b0), "r"(b1));
}
__device__ __forceinline__ void cpa16(uint32_t s, const bf16* g) {
    asm volatile("cp.async.cg.shared.global [%0], [%1], 16;"
                 :: "r"(s), "l"(__cvta_generic_to_global((const void*)g)) : "memory");
}
__device__ __forceinline__ void ldm4(uint32_t addr, uint32_t* r) {
    asm volatile("ldmatrix.sync.aligned.m8n8.x4.shared.b16 {%0,%1,%2,%3}, [%4];"
                 : "=r"(r[0]), "=r"(r[1]), "=r"(r[2]), "=r"(r[3]) : "r"(addr));
}

// block reductions for 256 threads: 1 barrier each (disjoint 8-word buffers)
__device__ __forceinline__ float blk_sum(float v, int tid, volatile float* red8) {
#pragma unroll
    for (int o = 16; o > 0; o >>= 1) v += __shfl_xor_sync(0xffffffffu, v, o);
    if ((tid & 31) == 0) red8[tid >> 5] = v;
    __syncthreads();
    float s = red8[tid & 7];
#pragma unroll
    for (int o = 4; o > 0; o >>= 1) s += __shfl_xor_sync(0xffffffffu, s, o);
    return s;
}
__device__ __forceinline__ float blk_max(float v, int tid, volatile float* red8) {
#pragma unroll
    for (int o = 16; o > 0; o >>= 1) v = fmaxf(v, __shfl_xor_sync(0xffffffffu, v, o));
    if ((tid & 31) == 0) red8[tid >> 5] = v;
    __syncthreads();
    float s = red8[tid & 7];
#pragma unroll
    for (int o = 4; o > 0; o >>= 1) s = fmaxf(s, __shfl_xor_sync(0xffffffffu, s, o));
    return s;
}

// ---------------- plane-operand GEMM: C = alpha * A(MxK) * B(NxK)^T ----------------
// Round-9 mainloop (verified optimum): single barrier per K-chunk.
// kstrB: element stride between successive KC=64 contraction chunks in B rows
// (64 for dense B; 128 to read K directly from the interleaved qkv layout).
__global__ __launch_bounds__(512, 1) void gemm_pp(
    const bf16* __restrict__ Ah, const bf16* __restrict__ Al,
    const bf16* __restrict__ Bh, const bf16* __restrict__ Bl,
    float* __restrict__ C, bf16* __restrict__ Ch, bf16* __restrict__ Cl,
    const float* __restrict__ bias,
    int K, int lda, int ldb, int ldc, int kstrB, Batch8 bt)
{
    extern __shared__ char dsm[];
    uint32_t base = smem_u32(dsm);
    base = (base + 1023u) & ~1023u;

    const int z = blockIdx.z;
    const bf16* gAh = Ah + bt.offA[z];
    const bf16* gAl = Al + bt.offA[z];
    const bf16* gBh = Bh + bt.offB[z];
    const bf16* gBl = Bl + bt.offB[z];
    const float alpha = bt.alpha[z];

    const int tid = threadIdx.x;
    const int lane = tid & 31;
    const int wid = tid >> 5;
    const int wm = wid >> 2, wn = wid & 3;
    const int bm = blockIdx.y * 128, bn = blockIdx.x * 256;

    // cp.async: per thread 4 A chunks (rows rowT+{0,32,64,96}) + 8 B chunks (+{0..224})
    const int rowT = tid >> 4;
    const int sub  = tid & 15;
    const int plane = sub >> 3;
    const int c4 = sub & 7;
    const bf16* aP = (plane ? gAl : gAh) + (size_t)(bm + rowT) * lda + c4 * 8;
    const bf16* bP = (plane ? gBl : gBh) + (size_t)(bn + rowT) * ldb + c4 * 8;
    const uint32_t swz = ((uint32_t)c4 * 16u) ^ (((uint32_t)rowT & 7u) << 4);
    const uint32_t sA = base + (uint32_t)rowT * 256u + (uint32_t)plane * 128u + swz;
    const uint32_t sB = base + 32768u + (uint32_t)rowT * 256u + (uint32_t)plane * 128u + swz;
    const size_t stepA = (size_t)32 * lda;
    const size_t stepB = (size_t)32 * ldb;

    // fragment addressing
    const int rA = lane & 15, khA = lane >> 4;
    const uint32_t abase = base + (uint32_t)(wm * 32 + rA) * 256u;
    const uint32_t swA = ((uint32_t)rA & 7u) << 4;
    const int rBr = (lane & 7) + ((lane >> 4) << 3);
    const int khB = (lane >> 3) & 1;
    const uint32_t bbase = base + 32768u + (uint32_t)(wn * 64 + rBr) * 256u;
    const uint32_t swB = ((uint32_t)rBr & 7u) << 4;

    float acc[2][8][4];
#pragma unroll
    for (int i = 0; i < 2; i++)
#pragma unroll
        for (int j = 0; j < 8; j++)
#pragma unroll
            for (int c = 0; c < 4; c++) acc[i][j][c] = 0.f;

    const int nk = K >> 6;

    // prologue: stage 0
#pragma unroll
    for (int i = 0; i < 4; i++) cpa16(sA + i * 8192u, aP + (size_t)i * stepA);
#pragma unroll
    for (int i = 0; i < 8; i++) cpa16(sB + i * 8192u, bP + (size_t)i * stepB);
    asm volatile("cp.async.commit_group;" ::: "memory");

    for (int kt = 0; kt < nk; kt++) {
        asm volatile("cp.async.wait_group 0;" ::: "memory");
        __syncthreads();
        if (kt + 1 < nk) {
            const uint32_t so2 = ((kt + 1) & 1) * (uint32_t)STG_BYTES;
            const int k0a = (kt + 1) << 6;
            const int k0b = (kt + 1) * kstrB;
#pragma unroll
            for (int i = 0; i < 4; i++) cpa16(sA + so2 + i * 8192u, aP + k0a + (size_t)i * stepA);
#pragma unroll
            for (int i = 0; i < 8; i++) cpa16(sB + so2 + i * 8192u, bP + k0b + (size_t)i * stepB);
            asm volatile("cp.async.commit_group;" ::: "memory");
        }
        const uint32_t so = (kt & 1) * (uint32_t)STG_BYTES;
        const uint32_t ab = abase + so;
        const uint32_t bb = bbase + so;
#pragma unroll
        for (int s = 0; s < 4; s++) {
            const uint32_t aoff = ((uint32_t)((s * 2 + khA) * 16)) ^ swA;
            const uint32_t boff = ((uint32_t)((s * 2 + khB) * 16)) ^ swB;
            uint32_t ah[2][4], al[2][4];
#pragma unroll
            for (int mb = 0; mb < 2; mb++) {
                ldm4(ab + mb * 4096 + aoff, ah[mb]);
                ldm4(ab + mb * 4096 + 128 + aoff, al[mb]);
            }
#pragma unroll
            for (int half = 0; half < 2; half++) {
                uint32_t bh[2][4], bl[2][4];
#pragma unroll
                for (int p2 = 0; p2 < 2; p2++) {
                    const int pr = half * 2 + p2;
                    ldm4(bb + pr * 4096 + boff, bh[p2]);
                    ldm4(bb + pr * 4096 + 128 + boff, bl[p2]);
                }
                // P1: Ah x Bh (8 MMAs, distinct accumulators)
#pragma unroll
                for (int p2 = 0; p2 < 2; p2++)
#pragma unroll
                    for (int nb2 = 0; nb2 < 2; nb2++)
#pragma unroll
                        for (int mb = 0; mb < 2; mb++)
                            mma_bf16(acc[mb][(half * 2 + p2) * 2 + nb2],
                                     ah[mb], bh[p2][nb2 * 2], bh[p2][nb2 * 2 + 1]);
                // P2: Ah x Bl
#pragma unroll
                for (int p2 = 0; p2 < 2; p2++)
#pragma unroll
                    for (int nb2 = 0; nb2 < 2; nb2++)
#pragma unroll
                        for (int mb = 0; mb < 2; mb++)
                            mma_bf16(acc[mb][(half * 2 + p2) * 2 + nb2],
                                     ah[mb], bl[p2][nb2 * 2], bl[p2][nb2 * 2 + 1]);
                // P3: Al x Bh
#pragma unroll
                for (int p2 = 0; p2 < 2; p2++)
#pragma unroll
                    for (int nb2 = 0; nb2 < 2; nb2++)
#pragma unroll
                        for (int mb = 0; mb < 2; mb++)
                            mma_bf16(acc[mb][(half * 2 + p2) * 2 + nb2],
                                     al[mb], bh[p2][nb2 * 2], bh[p2][nb2 * 2 + 1]);
            }
        }
    }

    // ---- epilogue ----
    const int qr = lane >> 2, qc = lane & 3;
    if (Ch) {
#pragma unroll
        for (int mb = 0; mb < 2; mb++) {
            const int row = bm + wm * 32 + mb * 16 + qr;
#pragma unroll
            for (int nb = 0; nb < 8; nb++) {
                const int col = bn + wn * 64 + nb * 8 + qc * 2;
                uint32_t h0, l0, h1, l1;
                split2(acc[mb][nb][0] * alpha, acc[mb][nb][1] * alpha, h0, l0);
                split2(acc[mb][nb][2] * alpha, acc[mb][nb][3] * alpha, h1, l1);
                const long long o0 = bt.offC[z] + (long long)row * ldc + col;
                const long long o1 = bt.offC[z] + (long long)(row + 8) * ldc + col;
                *(uint32_t*)(Ch + o0) = h0; *(uint32_t*)(Cl + o0) = l0;
                *(uint32_t*)(Ch + o1) = h1; *(uint32_t*)(Cl + o1) = l1;
            }
        }
    } else {
        float* Cz = C + bt.offC[z];
#pragma unroll
        for (int mb = 0; mb < 2; mb++) {
            const int row = bm + wm * 32 + mb * 16 + qr;
#pragma unroll
            for (int nb = 0; nb < 8; nb++) {
                const int col = bn + wn * 64 + nb * 8 + qc * 2;
                float2 v0, v1;
                v0.x = acc[mb][nb][0] * alpha;
                v0.y = acc[mb][nb][1] * alpha;
                v1.x = acc[mb][nb][2] * alpha;
                v1.y = acc[mb][nb][3] * alpha;
                if (bias) {
                    float2 bv = *(const float2*)(bias + col);
                    v0.x += bv.x; v0.y += bv.y;
                    v1.x += bv.x; v1.y += bv.y;
                }
                *(float2*)(Cz + (size_t)row * ldc + col) = v0;
                *(float2*)(Cz + (size_t)(row + 8) * ldc + col) = v1;
            }
        }
    }
}

// ---------------- weight split, layout: pw0|pw1 | (q0,kv0)|(q1,kv1) | ow0|ow1 ----------------
__global__ __launch_bounds__(256) void k_splitall(
    const float* __restrict__ pww, const float* __restrict__ qw,
    const float* __restrict__ kvw, const float* __restrict__ ow,
    bf16* __restrict__ h, bf16* __restrict__ l)
{
    long long i = (long long)blockIdx.x * 256 + threadIdx.x;
    const float* src;
    long long s;
    if (i < 1048576) { src = pww; s = i; }
    else if (i < 2621440) {
        long long j = i - 1048576;
        int layer = (int)(j / 786432);
        long long r = j - (long long)layer * 786432;
        if (r < 262144) { src = qw;  s = (long long)layer * 262144 + r; }
        else            { src = kvw; s = (long long)layer * 524288 + (r - 262144); }
    }
    else { src = ow; s = i - 2621440; }
    float4 v = ((const float4*)src)[s];
    uint32_t h0, l0, h1, l1;
    split2(v.x, v.y, h0, l0);
    split2(v.z, v.w, h1, l1);
    ((uint2*)h)[i] = make_uint2(h0, h1);
    ((uint2*)l)[i] = make_uint2(l0, l1);
}

// ---------------- Julia embedding ----------------
__global__ __launch_bounds__(256) void k_embed(
    const int* __restrict__ tok, const float* __restrict__ ctab,
    const float* __restrict__ projw, const float* __restrict__ escale,
    float* __restrict__ x)
{
    int bl = blockIdx.x;
    int t = tok[bl];
    float cr = ctab[2 * t], ci = ctab[2 * t + 1];
    float f[16];
    float zr = 0.f, zi = 0.f;
#pragma unroll
    for (int s = 0; s < 8; s++) {
        float nr = zr * zr - zi * zi + cr;
        float ni = 2.f * zr * zi + ci;
        zr = nr; zi = ni;
        f[2 * s] = zr; f[2 * s + 1] = zi;
    }
    float es = escale[0];
    int d0 = threadIdx.x * 4;
    float4 o;
    float* op = &o.x;
#pragma unroll
    for (int j = 0; j < 4; j++) {
        const float* w = projw + (size_t)(d0 + j) * 16;
        float acc = 0.f;
#pragma unroll
        for (int k = 0; k < 16; k++) acc = fmaf(f[k], w[k], acc);
        op[j] = acc * es;
    }
    *(float4*)(x + (size_t)bl * D_ + d0) = o;
}

// ---------------- depthwise conv (K=5), smem-tiled along l -> planes ----------------
__global__ __launch_bounds__(256) void k_dwconv(
    const float* __restrict__ x, const float* __restrict__ w,
    const float* __restrict__ bias, bf16* __restrict__ yh, bf16* __restrict__ yl)
{
    __shared__ float sx[36][256];
    const int lt = blockIdx.x;
    const int dc = blockIdx.y;
    const int b  = blockIdx.z;
    const int tid = threadIdx.x;
    const int l0 = lt * 32;
    const int d  = dc * 256 + tid;

    const float* xb = x + (size_t)b * L_ * D_ + d;
#pragma unroll
    for (int i = 0; i < 36; i++) {
        int ll = l0 - 2 + i;
        sx[i][tid] = (ll >= 0 && ll < L_) ? xb[(size_t)ll * D_] : 0.f;
    }
    __syncthreads();

    const float bsv = bias[d];
    float w0 = w[d * 5 + 0], w1 = w[d * 5 + 1], w2 = w[d * 5 + 2],
          w3 = w[d * 5 + 3], w4 = w[d * 5 + 4];
    bf16* oyh = yh + ((size_t)b * L_ + l0) * D_ + d;
    bf16* oyl = yl + ((size_t)b * L_ + l0) * D_ + d;
#pragma unroll
    for (int j = 0; j < 32; j++) {
        float acc = bsv;
        acc = fmaf(sx[j + 0][tid], w0, acc);
        acc = fmaf(sx[j + 1][tid], w1, acc);
        acc = fmaf(sx[j + 2][tid], w2, acc);
        acc = fmaf(sx[j + 3][tid], w3, acc);
        acc = fmaf(sx[j + 4][tid], w4, acc);
        bf16 h, lo;
        split1(acc, h, lo);
        oyh[(size_t)j * D_] = h;
        oyl[(size_t)j * D_] = lo;
    }
}

// ---------------- GLU + residual + LayerNorm -> fp32 x + planes ----------------
__global__ __launch_bounds__(256) void k_glu_ln(
    const float* __restrict__ x, const float* __restrict__ y2,
    const float* __restrict__ gbias, const float* __restrict__ lng,
    const float* __restrict__ lnb, float* __restrict__ out,
    bf16* __restrict__ oh, bf16* __restrict__ ol)
{
    __shared__ float redA[8], redB[8];
    int bl = blockIdx.x;
    int tid = threadIdx.x;
    int c = tid * 4;
    const float* xr = x + (size_t)bl * D_;
    const float* yr = y2 + (size_t)bl * 2 * D_;
    float4 xv = *(const float4*)(xr + c);
    float4 sv = *(const float4*)(yr + c);
    float4 gv = *(const float4*)(yr + D_ + c);
    float4 gb = *(const float4*)(gbias + c);
    float t0 = xv.x + sv.x * (1.f / (1.f + __expf(-(gv.x + gb.x))));
    float t1 = xv.y + sv.y * (1.f / (1.f + __expf(-(gv.y + gb.y))));
    float t2 = xv.z + sv.z * (1.f / (1.f + __expf(-(gv.z + gb.z))));
    float t3 = xv.w + sv.w * (1.f / (1.f + __expf(-(gv.w + gb.w))));

    float m = blk_sum(t0 + t1 + t2 + t3, tid, redA) * (1.f / 1024.f);
    float d0 = t0 - m, d1 = t1 - m, d2 = t2 - m, d3 = t3 - m;
    float var = blk_sum(d0 * d0 + d1 * d1 + d2 * d2 + d3 * d3, tid, redB);
    float inv = rsqrtf(var * (1.f / 1024.f) + 1e-5f);
    float4 gg = *(const float4*)(lng + c);
    float4 bb = *(const float4*)(lnb + c);
    float4 o4;
    o4.x = d0 * inv * gg.x + bb.x;
    o4.y = d1 * inv * gg.y + bb.y;
    o4.z = d2 * inv * gg.z + bb.z;
    o4.w = d3 * inv * gg.w + bb.w;
    size_t off = (size_t)bl * D_ + c;
    *(float4*)(out + off) = o4;
    uint32_t h0, l0, h1, l1;
    split2(o4.x, o4.y, h0, l0);
    split2(o4.z, o4.w, h1, l1);
    *(uint2*)(oh + off) = make_uint2(h0, h1);
    *(uint2*)(ol + off) = make_uint2(l0, l1);
}

// ---------------- residual add + LayerNorm ----------------
__global__ __launch_bounds__(256) void k_add_ln(
    const float* __restrict__ x, const float* __restrict__ zv,
    const float* __restrict__ lng, const float* __restrict__ lnb,
    float* __restrict__ out)
{
    __shared__ float redA[8], redB[8];
    int bl = blockIdx.x;
    int tid = threadIdx.x;
    int c = tid * 4;
    float4 xv = *(const float4*)(x + (size_t)bl * D_ + c);
    float4 zz = *(const float4*)(zv + (size_t)bl * D_ + c);
    float t0 = xv.x + zz.x, t1 = xv.y + zz.y, t2 = xv.z + zz.z, t3 = xv.w + zz.w;

    float m = blk_sum(t0 + t1 + t2 + t3, tid, redA) * (1.f / 1024.f);
    float d0 = t0 - m, d1 = t1 - m, d2 = t2 - m, d3 = t3 - m;
    float var = blk_sum(d0 * d0 + d1 * d1 + d2 * d2 + d3 * d3, tid, redB);
    float inv = rsqrtf(var * (1.f / 1024.f) + 1e-5f);
    float4 gg = *(const float4*)(lng + c);
    float4 bb = *(const float4*)(lnb + c);
    float4 o4;
    o4.x = d0 * inv * gg.x + bb.x;
    o4.y = d1 * inv * gg.y + bb.y;
    o4.z = d2 * inv * gg.z + bb.z;
    o4.w = d3 * inv * gg.w + bb.w;
    *(float4*)(out + (size_t)bl * D_ + c) = o4;
}

// ---------------- V transpose: plane permutation via smem tiles ----------------
__global__ __launch_bounds__(256) void k_packv(
    const bf16* __restrict__ kvh, const bf16* __restrict__ kvl,
    bf16* __restrict__ vth, bf16* __restrict__ vtl)
{
    __shared__ uint16_t th[64][66], tl[64][66];
    const int lt = blockIdx.x;
    const int h16 = blockIdx.y;
    const int b = blockIdx.z;
    const int l0 = lt * 64;
    const int tid = threadIdx.x;
    const int dcol = tid & 63;
    const int r4 = tid >> 6;
    const int G = h16 >> 3, h = h16 & 7;

#pragma unroll
    for (int i = 0; i < 16; i++) {
        int row = i * 4 + r4;
        size_t srow = ((size_t)b * L_ + l0 + row) * 3072 + 1024 + h16 * 128 + 64;
        th[row][dcol] = *(const uint16_t*)(kvh + srow + dcol);
        tl[row][dcol] = *(const uint16_t*)(kvl + srow + dcol);
    }
    __syncthreads();
#pragma unroll
    for (int i = 0; i < 16; i++) {
        int dim = i * 4 + r4;
        size_t o = ((size_t)b * 512 + h * 64 + dim) * 4096 + (size_t)G * 2048 + l0 + dcol;
        *(uint16_t*)(vth + o) = th[dcol][dim];
        *(uint16_t*)(vtl + o) = tl[dcol][dim];
    }
}

// ---------------- row softmax: stats + exp + split -> P planes ----------------
__global__ __launch_bounds__(256) void k_rowsoft(
    const float* __restrict__ S, bf16* __restrict__ Ph, bf16* __restrict__ Pl)
{
    __shared__ float redA[8], redB[8];
    const int l = blockIdx.x, G = blockIdx.y, bg = blockIdx.z;
    const size_t roff = ((size_t)bg * L_ + l) * 4096 + (size_t)G * 2048;
    const int tid = threadIdx.x;
    float v[8];
    *(float4*)(v)     = *(const float4*)(S + roff + tid * 8);
    *(float4*)(v + 4) = *(const float4*)(S + roff + tid * 8 + 4);
    float m = v[0];
#pragma unroll
    for (int j = 1; j < 8; j++) m = fmaxf(m, v[j]);
    m = blk_max(m, tid, redA);
    float e[8];
    float s = 0.f;
#pragma unroll
    for (int j = 0; j < 8; j++) { e[j] = __expf(v[j] - m); s += e[j]; }
    s = blk_sum(s, tid, redB);
    float inv = 1.f / s;
    uint4 ho, lo4;
    split2(e[0] * inv, e[1] * inv, ho.x, lo4.x);
    split2(e[2] * inv, e[3] * inv, ho.y, lo4.y);
    split2(e[4] * inv, e[5] * inv, ho.z, lo4.z);
    split2(e[6] * inv, e[7] * inv, ho.w, lo4.w);
    *(uint4*)(Ph + roff + tid * 8) = ho;
    *(uint4*)(Pl + roff + tid * 8) = lo4;
}

// ---------------- host ----------------
static void fill1(Batch8& bt)
{
    for (int z = 0; z < 8; z++) {
        bt.offA[z] = bt.offB[z] = bt.offC[z] = 0;
        bt.alpha[z] = 1.f;
    }
}

extern "C" void kernel_launch(void* const* d_in, const int* in_sizes, int n_in,
                              void* d_out, int out_size)
{
    (void)in_sizes; (void)n_in; (void)out_size;
    const int*   tok    = (const int*)  d_in[0];
    const float* ctab   = (const float*)d_in[1];
    const float* projw  = (const float*)d_in[2];
    const float* escale = (const float*)d_in[3];
    const float* dww    = (const float*)d_in[4];
    const float* dwb    = (const float*)d_in[5];
    const float* pww    = (const float*)d_in[6];
    const float* pwb    = (const float*)d_in[7];
    const float* gbias  = (const float*)d_in[8];
    const float* clng   = (const float*)d_in[9];
    const float* clnb   = (const float*)d_in[10];
    const float* qw     = (const float*)d_in[11];
    const float* kvw    = (const float*)d_in[12];
    const float* ow     = (const float*)d_in[13];
    const float* alng   = (const float*)d_in[14];
    const float* alnb   = (const float*)d_in[15];

    cudaFuncSetAttribute(gemm_pp, cudaFuncAttributeMaxDynamicSharedMemorySize, GEMM_SMEM);

    float *x, *t2, *q, *S;
    cudaGetSymbolAddress((void**)&x,  g_x);
    cudaGetSymbolAddress((void**)&t2, g_t2);
    cudaGetSymbolAddress((void**)&q,  g_q);
    cudaGetSymbolAddress((void**)&S,  g_s);
    bf16 *t1h, *t1l, *xh, *xl, *qkvh, *qkvl, *vth, *vtl, *Ph, *Pl, *Wh, *Wl;
    cudaGetSymbolAddress((void**)&t1h, p_t1h);   cudaGetSymbolAddress((void**)&t1l, p_t1l);
    cudaGetSymbolAddress((void**)&xh,  p_xh);    cudaGetSymbolAddress((void**)&xl,  p_xl);
    cudaGetSymbolAddress((void**)&qkvh, p_qkvh); cudaGetSymbolAddress((void**)&qkvl, p_qkvl);
    cudaGetSymbolAddress((void**)&vth, p_vth);   cudaGetSymbolAddress((void**)&vtl, p_vtl);
    cudaGetSymbolAddress((void**)&Ph,  p_Ph);    cudaGetSymbolAddress((void**)&Pl,  p_Pl);
    cudaGetSymbolAddress((void**)&Wh,  p_Wh);    cudaGetSymbolAddress((void**)&Wl,  p_Wl);

    // weight plane layout: pw_i @ i*2097152 | qkv_i @ 4194304 + i*3145728 | ow_i @ 10485760 + i*1048576
    k_splitall<<<12288, 256>>>(pww, qw, kvw, ow, Wh, Wl);

    k_embed<<<B_ * L_, 256>>>(tok, ctab, projw, escale, x);

    for (int i = 0; i < 2; i++) {
        // --- conv block ---
        k_dwconv<<<dim3(64, 4, 2), 256>>>(x, dww + (size_t)i * D_ * 5, dwb + i * D_,
                                          t1h, t1l);

        Batch8 b1; fill1(b1);
        gemm_pp<<<dim3(8, 32, 1), 512, GEMM_SMEM>>>(
            t1h, t1l, Wh + (long long)i * 2097152, Wl + (long long)i * 2097152,
            t2, nullptr, nullptr, pwb + i * 2048, 1024, 1024, 1024, 2048, 64, b1);

        k_glu_ln<<<B_ * L_, 256>>>(x, t2, gbias + i * D_, clng + i * D_, clnb + i * D_,
                                   x, xh, xl);

        // --- attention block ---
        const long long OQKV = 4194304 + (long long)i * 3145728;
        gemm_pp<<<dim3(12, 32, 1), 512, GEMM_SMEM>>>(
            xh, xl, Wh + OQKV, Wl + OQKV,
            nullptr, qkvh, qkvl, nullptr, 1024, 1024, 1024, 3072, 64, b1);

        k_packv<<<dim3(32, 16, 2), 256>>>(qkvh, qkvl, vth, vtl);

        // scores: B = K read directly from qkv planes (chunk kt = head kt, stride 128)
        Batch8 bs; fill1(bs);
        for (int zz = 0; zz < 8; zz++) {
            int bg = zz >> 1, G = zz & 1;
            int b = bg >> 1, g = bg & 1;
            bs.offA[zz] = (long long)b * L_ * 3072 + g * 512;
            bs.offB[zz] = (long long)b * L_ * 3072 + 1024 + (long long)G * 1024;
            bs.offC[zz] = (long long)bg * L_ * 4096 + G * 2048;
            bs.alpha[zz] = 0.125f * (G ? 2.0f : 1.0f);
        }
        gemm_pp<<<dim3(8, 16, 8), 512, GEMM_SMEM>>>(
            qkvh, qkvl, qkvh, qkvl, S, nullptr, nullptr, nullptr,
            512, 3072, 3072, 4096, 128, bs);

        k_rowsoft<<<dim3(L_, 2, 4), 256>>>(S, Ph, Pl);

        Batch8 bo; fill1(bo);
        for (int zz = 0; zz < 4; zz++) {
            int b = zz >> 1, g = zz & 1;
            bo.offA[zz] = (long long)zz * L_ * 4096;
            bo.offB[zz] = (long long)b * 512 * 4096;
            bo.offC[zz] = (long long)b * L_ * 1024 + g * 512;
        }
        gemm_pp<<<dim3(2, 16, 4), 512, GEMM_SMEM>>>(
            Ph, Pl, vth, vtl, nullptr, t1h, t1l, nullptr, 4096, 4096, 4096, 1024, 64, bo);

        const long long OOW = 10485760 + (long long)i * 1048576;
        gemm_pp<<<dim3(4, 32, 1), 512, GEMM_SMEM>>>(
            t1h, t1l, Wh + OOW, Wl + OOW,
            q, nullptr, nullptr, nullptr, 1024, 1024, 1024, 1024, 64, b1);

        float* dst = (i == 1) ? (float*)d_out : x;
        k_add_ln<<<B_ * L_, 256>>>(x, q, alng + i * D_, alnb + i * D_, dst);
    }
}

// round 17
// speedup vs baseline: 1.0276x; 1.0044x over previous
#include <cuda_runtime.h>
#include <cuda_bf16.h>
#include <math.h>
#include <stdint.h>

#define D_ 1024
#define L_ 2048
#define B_ 2

typedef __nv_bfloat16 bf16;

// GEMM: CTA 128x256, 512 thr, warps 4M x 4N (32x64 each), KC=64, 2-stage cp.async
#define STG_BYTES 98304
#define GEMM_SMEM (2 * STG_BYTES + 1024)

// ---------------- fp32 scratch ----------------
__device__ float g_x [B_ * L_ * D_];
__device__ float g_t2[B_ * L_ * 2 * D_];
__device__ float g_q [B_ * L_ * D_];
__device__ float g_s [4LL * L_ * 4096];

// ---------------- bf16 hi/lo planes ----------------
__device__ __align__(16) bf16 p_t1h [B_ * L_ * D_],       p_t1l [B_ * L_ * D_];
__device__ __align__(16) bf16 p_xh  [B_ * L_ * D_],       p_xl  [B_ * L_ * D_];
__device__ __align__(16) bf16 p_qkvh[B_ * L_ * 3072],     p_qkvl[B_ * L_ * 3072];
__device__ __align__(16) bf16 p_vth [B_ * 512 * 2 * L_],  p_vtl [B_ * 512 * 2 * L_];
__device__ __align__(16) bf16 p_Ph  [4LL * L_ * 4096],    p_Pl  [4LL * L_ * 4096];
__device__ __align__(16) bf16 p_Wh  [12 * 1024 * 1024],   p_Wl  [12 * 1024 * 1024];

struct Batch8 {
    long long offA[8];
    long long offB[8];
    long long offC[8];
    float alpha[8];
};

// ---------------- helpers ----------------
__device__ __forceinline__ uint32_t smem_u32(const void* p) {
    uint32_t a;
    asm("{ .reg .u64 t; cvta.to.shared.u64 t, %1; cvt.u32.u64 %0, t; }" : "=r"(a) : "l"(p));
    return a;
}
__device__ __forceinline__ void split2(float a, float b, uint32_t& hi, uint32_t& lo) {
    uint32_t h;
    asm("cvt.rn.satfinite.bf16x2.f32 %0, %1, %2;" : "=r"(h) : "f"(b), "f"(a));
    float ra = a - __uint_as_float(h << 16);
    float rb = b - __uint_as_float(h & 0xffff0000u);
    uint32_t l;
    asm("cvt.rn.satfinite.bf16x2.f32 %0, %1, %2;" : "=r"(l) : "f"(rb), "f"(ra));
    hi = h; lo = l;
}
__device__ __forceinline__ void split1(float a, bf16& h, bf16& l) {
    h = __float2bfloat16_rn(a);
    l = __float2bfloat16_rn(a - __bfloat162float(h));
}
// non-volatile: lets ptxas interleave HMMAs with LDSMs
__device__ __forceinline__ void mma_bf16(float* c, const uint32_t* a, uint32_t b0, uint32_t b1) {
    asm("mma.sync.aligned.m16n8k16.row.col.f32.bf16.bf16.f32 "
        "{%0,%1,%2,%3}, {%4,%5,%6,%7}, {%8,%9}, {%0,%1,%2,%3};"
        : "+f"(c[0]), "+f"(c[1]), "+f"(c[2]), "+f"(c[3])
        : "r"(a[0]), "r"(a[1]), "r"(a[2]), "r"(a[3]), "r"(b0), "r"(b1));
}
__device__ __forceinline__ void cpa16(uint32_t s, const bf16* g) {
    asm volatile("cp.async.cg.shared.global [%0], [%1], 16;"
                 :: "r"(s), "l"(__cvta_generic_to_global((const void*)g)) : "memory");
}
__device__ __forceinline__ void ldm4(uint32_t addr, uint32_t* r) {
    asm volatile("ldmatrix.sync.aligned.m8n8.x4.shared.b16 {%0,%1,%2,%3}, [%4];"
                 : "=r"(r[0]), "=r"(r[1]), "=r"(r[2]), "=r"(r[3]) : "r"(addr));
}

// block reductions for 256 threads: 1 barrier each (disjoint 8-word buffers)
__device__ __forceinline__ float blk_sum(float v, int tid, volatile float* red8) {
#pragma unroll
    for (int o = 16; o > 0; o >>= 1) v += __shfl_xor_sync(0xffffffffu, v, o);
    if ((tid & 31) == 0) red8[tid >> 5] = v;
    __syncthreads();
    float s = red8[tid & 7];
#pragma unroll
    for (int o = 4; o > 0; o >>= 1) s += __shfl_xor_sync(0xffffffffu, s, o);
    return s;
}
__device__ __forceinline__ float blk_max(float v, int tid, volatile float* red8) {
#pragma unroll
    for (int o = 16; o > 0; o >>= 1) v = fmaxf(v, __shfl_xor_sync(0xffffffffu, v, o));
    if ((tid & 31) == 0) red8[tid >> 5] = v;
    __syncthreads();
    float s = red8[tid & 7];
#pragma unroll
    for (int o = 4; o > 0; o >>= 1) s = fmaxf(s, __shfl_xor_sync(0xffffffffu, s, o));
    return s;
}

// ---------------- plane-operand GEMM: C = alpha * A(MxK) * B(NxK)^T ----------------
// Round-9 mainloop (verified optimum): single barrier per K-chunk.
// kstrB: element stride between successive KC=64 contraction chunks in B rows.
__global__ __launch_bounds__(512, 1) void gemm_pp(
    const bf16* __restrict__ Ah, const bf16* __restrict__ Al,
    const bf16* __restrict__ Bh, const bf16* __restrict__ Bl,
    float* __restrict__ C, bf16* __restrict__ Ch, bf16* __restrict__ Cl,
    const float* __restrict__ bias,
    int K, int lda, int ldb, int ldc, int kstrB, Batch8 bt)
{
    extern __shared__ char dsm[];
    uint32_t base = smem_u32(dsm);
    base = (base + 1023u) & ~1023u;

    const int z = blockIdx.z;
    const bf16* gAh = Ah + bt.offA[z];
    const bf16* gAl = Al + bt.offA[z];
    const bf16* gBh = Bh + bt.offB[z];
    const bf16* gBl = Bl + bt.offB[z];
    const float alpha = bt.alpha[z];

    const int tid = threadIdx.x;
    const int lane = tid & 31;
    const int wid = tid >> 5;
    const int wm = wid >> 2, wn = wid & 3;
    const int bm = blockIdx.y * 128, bn = blockIdx.x * 256;

    const int rowT = tid >> 4;
    const int sub  = tid & 15;
    const int plane = sub >> 3;
    const int c4 = sub & 7;
    const bf16* aP = (plane ? gAl : gAh) + (size_t)(bm + rowT) * lda + c4 * 8;
    const bf16* bP = (plane ? gBl : gBh) + (size_t)(bn + rowT) * ldb + c4 * 8;
    const uint32_t swz = ((uint32_t)c4 * 16u) ^ (((uint32_t)rowT & 7u) << 4);
    const uint32_t sA = base + (uint32_t)rowT * 256u + (uint32_t)plane * 128u + swz;
    const uint32_t sB = base + 32768u + (uint32_t)rowT * 256u + (uint32_t)plane * 128u + swz;
    const size_t stepA = (size_t)32 * lda;
    const size_t stepB = (size_t)32 * ldb;

    const int rA = lane & 15, khA = lane >> 4;
    const uint32_t abase = base + (uint32_t)(wm * 32 + rA) * 256u;
    const uint32_t swA = ((uint32_t)rA & 7u) << 4;
    const int rBr = (lane & 7) + ((lane >> 4) << 3);
    const int khB = (lane >> 3) & 1;
    const uint32_t bbase = base + 32768u + (uint32_t)(wn * 64 + rBr) * 256u;
    const uint32_t swB = ((uint32_t)rBr & 7u) << 4;

    float acc[2][8][4];
#pragma unroll
    for (int i = 0; i < 2; i++)
#pragma unroll
        for (int j = 0; j < 8; j++)
#pragma unroll
            for (int c = 0; c < 4; c++) acc[i][j][c] = 0.f;

    const int nk = K >> 6;

#pragma unroll
    for (int i = 0; i < 4; i++) cpa16(sA + i * 8192u, aP + (size_t)i * stepA);
#pragma unroll
    for (int i = 0; i < 8; i++) cpa16(sB + i * 8192u, bP + (size_t)i * stepB);
    asm volatile("cp.async.commit_group;" ::: "memory");

    for (int kt = 0; kt < nk; kt++) {
        asm volatile("cp.async.wait_group 0;" ::: "memory");
        __syncthreads();
        if (kt + 1 < nk) {
            const uint32_t so2 = ((kt + 1) & 1) * (uint32_t)STG_BYTES;
            const int k0a = (kt + 1) << 6;
            const int k0b = (kt + 1) * kstrB;
#pragma unroll
            for (int i = 0; i < 4; i++) cpa16(sA + so2 + i * 8192u, aP + k0a + (size_t)i * stepA);
#pragma unroll
            for (int i = 0; i < 8; i++) cpa16(sB + so2 + i * 8192u, bP + k0b + (size_t)i * stepB);
            asm volatile("cp.async.commit_group;" ::: "memory");
        }
        const uint32_t so = (kt & 1) * (uint32_t)STG_BYTES;
        const uint32_t ab = abase + so;
        const uint32_t bb = bbase + so;
#pragma unroll
        for (int s = 0; s < 4; s++) {
            const uint32_t aoff = ((uint32_t)((s * 2 + khA) * 16)) ^ swA;
            const uint32_t boff = ((uint32_t)((s * 2 + khB) * 16)) ^ swB;
            uint32_t ah[2][4], al[2][4];
#pragma unroll
            for (int mb = 0; mb < 2; mb++) {
                ldm4(ab + mb * 4096 + aoff, ah[mb]);
                ldm4(ab + mb * 4096 + 128 + aoff, al[mb]);
            }
#pragma unroll
            for (int half = 0; half < 2; half++) {
                uint32_t bh[2][4], bl[2][4];
#pragma unroll
                for (int p2 = 0; p2 < 2; p2++) {
                    const int pr = half * 2 + p2;
                    ldm4(bb + pr * 4096 + boff, bh[p2]);
                    ldm4(bb + pr * 4096 + 128 + boff, bl[p2]);
                }
#pragma unroll
                for (int p2 = 0; p2 < 2; p2++)
#pragma unroll
                    for (int nb2 = 0; nb2 < 2; nb2++)
#pragma unroll
                        for (int mb = 0; mb < 2; mb++)
                            mma_bf16(acc[mb][(half * 2 + p2) * 2 + nb2],
                                     ah[mb], bh[p2][nb2 * 2], bh[p2][nb2 * 2 + 1]);
#pragma unroll
                for (int p2 = 0; p2 < 2; p2++)
#pragma unroll
                    for (int nb2 = 0; nb2 < 2; nb2++)
#pragma unroll
                        for (int mb = 0; mb < 2; mb++)
                            mma_bf16(acc[mb][(half * 2 + p2) * 2 + nb2],
                                     ah[mb], bl[p2][nb2 * 2], bl[p2][nb2 * 2 + 1]);
#pragma unroll
                for (int p2 = 0; p2 < 2; p2++)
#pragma unroll
                    for (int nb2 = 0; nb2 < 2; nb2++)
#pragma unroll
                        for (int mb = 0; mb < 2; mb++)
                            mma_bf16(acc[mb][(half * 2 + p2) * 2 + nb2],
                                     al[mb], bh[p2][nb2 * 2], bh[p2][nb2 * 2 + 1]);
            }
        }
    }

    // ---- epilogue ----
    const int qr = lane >> 2, qc = lane & 3;
    if (Ch) {
#pragma unroll
        for (int mb = 0; mb < 2; mb++) {
            const int row = bm + wm * 32 + mb * 16 + qr;
#pragma unroll
            for (int nb = 0; nb < 8; nb++) {
                const int col = bn + wn * 64 + nb * 8 + qc * 2;
                uint32_t h0, l0, h1, l1;
                split2(acc[mb][nb][0] * alpha, acc[mb][nb][1] * alpha, h0, l0);
                split2(acc[mb][nb][2] * alpha, acc[mb][nb][3] * alpha, h1, l1);
                const long long o0 = bt.offC[z] + (long long)row * ldc + col;
                const long long o1 = bt.offC[z] + (long long)(row + 8) * ldc + col;
                *(uint32_t*)(Ch + o0) = h0; *(uint32_t*)(Cl + o0) = l0;
                *(uint32_t*)(Ch + o1) = h1; *(uint32_t*)(Cl + o1) = l1;
            }
        }
    } else {
        float* Cz = C + bt.offC[z];
#pragma unroll
        for (int mb = 0; mb < 2; mb++) {
            const int row = bm + wm * 32 + mb * 16 + qr;
#pragma unroll
            for (int nb = 0; nb < 8; nb++) {
                const int col = bn + wn * 64 + nb * 8 + qc * 2;
                float2 v0, v1;
                v0.x = acc[mb][nb][0] * alpha;
                v0.y = acc[mb][nb][1] * alpha;
                v1.x = acc[mb][nb][2] * alpha;
                v1.y = acc[mb][nb][3] * alpha;
                if (bias) {
                    float2 bv = *(const float2*)(bias + col);
                    v0.x += bv.x; v0.y += bv.y;
                    v1.x += bv.x; v1.y += bv.y;
                }
                *(float2*)(Cz + (size_t)row * ldc + col) = v0;
                *(float2*)(Cz + (size_t)(row + 8) * ldc + col) = v1;
            }
        }
    }
}

// ---------------- weight split, layout: pw0|pw1 | (q0,kv0)|(q1,kv1) | ow0|ow1 ----------------
__global__ __launch_bounds__(256) void k_splitall(
    const float* __restrict__ pww, const float* __restrict__ qw,
    const float* __restrict__ kvw, const float* __restrict__ ow,
    bf16* __restrict__ h, bf16* __restrict__ l)
{
    long long i = (long long)blockIdx.x * 256 + threadIdx.x;
    const float* src;
    long long s;
    if (i < 1048576) { src = pww; s = i; }
    else if (i < 2621440) {
        long long j = i - 1048576;
        int layer = (int)(j / 786432);
        long long r = j - (long long)layer * 786432;
        if (r < 262144) { src = qw;  s = (long long)layer * 262144 + r; }
        else            { src = kvw; s = (long long)layer * 524288 + (r - 262144); }
    }
    else { src = ow; s = i - 2621440; }
    float4 v = ((const float4*)src)[s];
    uint32_t h0, l0, h1, l1;
    split2(v.x, v.y, h0, l0);
    split2(v.z, v.w, h1, l1);
    ((uint2*)h)[i] = make_uint2(h0, h1);
    ((uint2*)l)[i] = make_uint2(l0, l1);
}

// ---------------- Julia embedding ----------------
__global__ __launch_bounds__(256) void k_embed(
    const int* __restrict__ tok, const float* __restrict__ ctab,
    const float* __restrict__ projw, const float* __restrict__ escale,
    float* __restrict__ x)
{
    int bl = blockIdx.x;
    int t = tok[bl];
    float cr = ctab[2 * t], ci = ctab[2 * t + 1];
    float f[16];
    float zr = 0.f, zi = 0.f;
#pragma unroll
    for (int s = 0; s < 8; s++) {
        float nr = zr * zr - zi * zi + cr;
        float ni = 2.f * zr * zi + ci;
        zr = nr; zi = ni;
        f[2 * s] = zr; f[2 * s + 1] = zi;
    }
    float es = escale[0];
    int d0 = threadIdx.x * 4;
    float4 o;
    float* op = &o.x;
#pragma unroll
    for (int j = 0; j < 4; j++) {
        const float* w = projw + (size_t)(d0 + j) * 16;
        float acc = 0.f;
#pragma unroll
        for (int k = 0; k < 16; k++) acc = fmaf(f[k], w[k], acc);
        op[j] = acc * es;
    }
    *(float4*)(x + (size_t)bl * D_ + d0) = o;
}

// ---------------- depthwise conv (K=5), smem-tiled along l -> planes ----------------
__global__ __launch_bounds__(256) void k_dwconv(
    const float* __restrict__ x, const float* __restrict__ w,
    const float* __restrict__ bias, bf16* __restrict__ yh, bf16* __restrict__ yl)
{
    __shared__ float sx[36][256];
    const int lt = blockIdx.x;
    const int dc = blockIdx.y;
    const int b  = blockIdx.z;
    const int tid = threadIdx.x;
    const int l0 = lt * 32;
    const int d  = dc * 256 + tid;

    const float* xb = x + (size_t)b * L_ * D_ + d;
#pragma unroll
    for (int i = 0; i < 36; i++) {
        int ll = l0 - 2 + i;
        sx[i][tid] = (ll >= 0 && ll < L_) ? xb[(size_t)ll * D_] : 0.f;
    }
    __syncthreads();

    const float bsv = bias[d];
    float w0 = w[d * 5 + 0], w1 = w[d * 5 + 1], w2 = w[d * 5 + 2],
          w3 = w[d * 5 + 3], w4 = w[d * 5 + 4];
    bf16* oyh = yh + ((size_t)b * L_ + l0) * D_ + d;
    bf16* oyl = yl + ((size_t)b * L_ + l0) * D_ + d;
#pragma unroll
    for (int j = 0; j < 32; j++) {
        float acc = bsv;
        acc = fmaf(sx[j + 0][tid], w0, acc);
        acc = fmaf(sx[j + 1][tid], w1, acc);
        acc = fmaf(sx[j + 2][tid], w2, acc);
        acc = fmaf(sx[j + 3][tid], w3, acc);
        acc = fmaf(sx[j + 4][tid], w4, acc);
        bf16 h, lo;
        split1(acc, h, lo);
        oyh[(size_t)j * D_] = h;
        oyl[(size_t)j * D_] = lo;
    }
}

// ---------------- GLU + residual + LayerNorm -> fp32 x + planes ----------------
__global__ __launch_bounds__(256) void k_glu_ln(
    const float* __restrict__ x, const float* __restrict__ y2,
    const float* __restrict__ gbias, const float* __restrict__ lng,
    const float* __restrict__ lnb, float* __restrict__ out,
    bf16* __restrict__ oh, bf16* __restrict__ ol)
{
    __shared__ float redA[8], redB[8];
    int bl = blockIdx.x;
    int tid = threadIdx.x;
    int c = tid * 4;
    const float* xr = x + (size_t)bl * D_;
    const float* yr = y2 + (size_t)bl * 2 * D_;
    float4 xv = *(const float4*)(xr + c);
    float4 sv = *(const float4*)(yr + c);
    float4 gv = *(const float4*)(yr + D_ + c);
    float4 gb = *(const float4*)(gbias + c);
    float t0 = xv.x + sv.x * (1.f / (1.f + __expf(-(gv.x + gb.x))));
    float t1 = xv.y + sv.y * (1.f / (1.f + __expf(-(gv.y + gb.y))));
    float t2 = xv.z + sv.z * (1.f / (1.f + __expf(-(gv.z + gb.z))));
    float t3 = xv.w + sv.w * (1.f / (1.f + __expf(-(gv.w + gb.w))));

    float m = blk_sum(t0 + t1 + t2 + t3, tid, redA) * (1.f / 1024.f);
    float d0 = t0 - m, d1 = t1 - m, d2 = t2 - m, d3 = t3 - m;
    float var = blk_sum(d0 * d0 + d1 * d1 + d2 * d2 + d3 * d3, tid, redB);
    float inv = rsqrtf(var * (1.f / 1024.f) + 1e-5f);
    float4 gg = *(const float4*)(lng + c);
    float4 bb = *(const float4*)(lnb + c);
    float4 o4;
    o4.x = d0 * inv * gg.x + bb.x;
    o4.y = d1 * inv * gg.y + bb.y;
    o4.z = d2 * inv * gg.z + bb.z;
    o4.w = d3 * inv * gg.w + bb.w;
    size_t off = (size_t)bl * D_ + c;
    *(float4*)(out + off) = o4;
    uint32_t h0, l0, h1, l1;
    split2(o4.x, o4.y, h0, l0);
    split2(o4.z, o4.w, h1, l1);
    *(uint2*)(oh + off) = make_uint2(h0, h1);
    *(uint2*)(ol + off) = make_uint2(l0, l1);
}

// ---------------- residual add + LayerNorm ----------------
__global__ __launch_bounds__(256) void k_add_ln(
    const float* __restrict__ x, const float* __restrict__ zv,
    const float* __restrict__ lng, const float* __restrict__ lnb,
    float* __restrict__ out)
{
    __shared__ float redA[8], redB[8];
    int bl = blockIdx.x;
    int tid = threadIdx.x;
    int c = tid * 4;
    float4 xv = *(const float4*)(x + (size_t)bl * D_ + c);
    float4 zz = *(const float4*)(zv + (size_t)bl * D_ + c);
    float t0 = xv.x + zz.x, t1 = xv.y + zz.y, t2 = xv.z + zz.z, t3 = xv.w + zz.w;

    float m = blk_sum(t0 + t1 + t2 + t3, tid, redA) * (1.f / 1024.f);
    float d0 = t0 - m, d1 = t1 - m, d2 = t2 - m, d3 = t3 - m;
    float var = blk_sum(d0 * d0 + d1 * d1 + d2 * d2 + d3 * d3, tid, redB);
    float inv = rsqrtf(var * (1.f / 1024.f) + 1e-5f);
    float4 gg = *(const float4*)(lng + c);
    float4 bb = *(const float4*)(lnb + c);
    float4 o4;
    o4.x = d0 * inv * gg.x + bb.x;
    o4.y = d1 * inv * gg.y + bb.y;
    o4.z = d2 * inv * gg.z + bb.z;
    o4.w = d3 * inv * gg.w + bb.w;
    *(float4*)(out + (size_t)bl * D_ + c) = o4;
}

// ---------------- V transpose: plane permutation via smem tiles ----------------
__global__ __launch_bounds__(256) void k_packv(
    const bf16* __restrict__ kvh, const bf16* __restrict__ kvl,
    bf16* __restrict__ vth, bf16* __restrict__ vtl)
{
    __shared__ uint16_t th[64][66], tl[64][66];
    const int lt = blockIdx.x;
    const int h16 = blockIdx.y;
    const int b = blockIdx.z;
    const int l0 = lt * 64;
    const int tid = threadIdx.x;
    const int dcol = tid & 63;
    const int r4 = tid >> 6;
    const int G = h16 >> 3, h = h16 & 7;

#pragma unroll
    for (int i = 0; i < 16; i++) {
        int row = i * 4 + r4;
        size_t srow = ((size_t)b * L_ + l0 + row) * 3072 + 1024 + h16 * 128 + 64;
        th[row][dcol] = *(const uint16_t*)(kvh + srow + dcol);
        tl[row][dcol] = *(const uint16_t*)(kvl + srow + dcol);
    }
    __syncthreads();
#pragma unroll
    for (int i = 0; i < 16; i++) {
        int dim = i * 4 + r4;
        size_t o = ((size_t)b * 512 + h * 64 + dim) * 4096 + (size_t)G * 2048 + l0 + dcol;
        *(uint16_t*)(vth + o) = th[dcol][dim];
        *(uint16_t*)(vtl + o) = tl[dcol][dim];
    }
}

// ---------------- row softmax: stats + exp + split -> P planes ----------------
__global__ __launch_bounds__(256) void k_rowsoft(
    const float* __restrict__ S, bf16* __restrict__ Ph, bf16* __restrict__ Pl)
{
    __shared__ float redA[8], redB[8];
    const int l = blockIdx.x, G = blockIdx.y, bg = blockIdx.z;
    const size_t roff = ((size_t)bg * L_ + l) * 4096 + (size_t)G * 2048;
    const int tid = threadIdx.x;
    float v[8];
    *(float4*)(v)     = *(const float4*)(S + roff + tid * 8);
    *(float4*)(v + 4) = *(const float4*)(S + roff + tid * 8 + 4);
    float m = v[0];
#pragma unroll
    for (int j = 1; j < 8; j++) m = fmaxf(m, v[j]);
    m = blk_max(m, tid, redA);
    float e[8];
    float s = 0.f;
#pragma unroll
    for (int j = 0; j < 8; j++) { e[j] = __expf(v[j] - m); s += e[j]; }
    s = blk_sum(s, tid, redB);
    float inv = 1.f / s;
    uint4 ho, lo4;
    split2(e[0] * inv, e[1] * inv, ho.x, lo4.x);
    split2(e[2] * inv, e[3] * inv, ho.y, lo4.y);
    split2(e[4] * inv, e[5] * inv, ho.z, lo4.z);
    split2(e[6] * inv, e[7] * inv, ho.w, lo4.w);
    *(uint4*)(Ph + roff + tid * 8) = ho;
    *(uint4*)(Pl + roff + tid * 8) = lo4;
}

// ---------------- host ----------------
static void fill1(Batch8& bt)
{
    for (int z = 0; z < 8; z++) {
        bt.offA[z] = bt.offB[z] = bt.offC[z] = 0;
        bt.alpha[z] = 1.f;
    }
}

extern "C" void kernel_launch(void* const* d_in, const int* in_sizes, int n_in,
                              void* d_out, int out_size)
{
    (void)in_sizes; (void)n_in; (void)out_size;
    const int*   tok    = (const int*)  d_in[0];
    const float* ctab   = (const float*)d_in[1];
    const float* projw  = (const float*)d_in[2];
    const float* escale = (const float*)d_in[3];
    const float* dww    = (const float*)d_in[4];
    const float* dwb    = (const float*)d_in[5];
    const float* pww    = (const float*)d_in[6];
    const float* pwb    = (const float*)d_in[7];
    const float* gbias  = (const float*)d_in[8];
    const float* clng   = (const float*)d_in[9];
    const float* clnb   = (const float*)d_in[10];
    const float* qw     = (const float*)d_in[11];
    const float* kvw    = (const float*)d_in[12];
    const float* ow     = (const float*)d_in[13];
    const float* alng   = (const float*)d_in[14];
    const float* alnb   = (const float*)d_in[15];

    cudaFuncSetAttribute(gemm_pp, cudaFuncAttributeMaxDynamicSharedMemorySize, GEMM_SMEM);

    // side stream + fork/join events (created once; graph-capture legal)
    static cudaStream_t s2 = nullptr;
    static cudaEvent_t evFork0 = nullptr, evJoin0 = nullptr;
    static cudaEvent_t evFork1 = nullptr, evJoin1 = nullptr;
    if (s2 == nullptr) {
        cudaStreamCreateWithFlags(&s2, cudaStreamNonBlocking);
        cudaEventCreateWithFlags(&evFork0, cudaEventDisableTiming);
        cudaEventCreateWithFlags(&evJoin0, cudaEventDisableTiming);
        cudaEventCreateWithFlags(&evFork1, cudaEventDisableTiming);
        cudaEventCreateWithFlags(&evJoin1, cudaEventDisableTiming);
    }

    float *x, *t2, *q, *S;
    cudaGetSymbolAddress((void**)&x,  g_x);
    cudaGetSymbolAddress((void**)&t2, g_t2);
    cudaGetSymbolAddress((void**)&q,  g_q);
    cudaGetSymbolAddress((void**)&S,  g_s);
    bf16 *t1h, *t1l, *xh, *xl, *qkvh, *qkvl, *vth, *vtl, *Ph, *Pl, *Wh, *Wl;
    cudaGetSymbolAddress((void**)&t1h, p_t1h);   cudaGetSymbolAddress((void**)&t1l, p_t1l);
    cudaGetSymbolAddress((void**)&xh,  p_xh);    cudaGetSymbolAddress((void**)&xl,  p_xl);
    cudaGetSymbolAddress((void**)&qkvh, p_qkvh); cudaGetSymbolAddress((void**)&qkvl, p_qkvl);
    cudaGetSymbolAddress((void**)&vth, p_vth);   cudaGetSymbolAddress((void**)&vtl, p_vtl);
    cudaGetSymbolAddress((void**)&Ph,  p_Ph);    cudaGetSymbolAddress((void**)&Pl,  p_Pl);
    cudaGetSymbolAddress((void**)&Wh,  p_Wh);    cudaGetSymbolAddress((void**)&Wl,  p_Wl);

    // fork: weight split on s2, overlapped with embed + first dwconv on stream 0
    cudaEventRecord(evFork0, 0);
    cudaStreamWaitEvent(s2, evFork0, 0);
    k_splitall<<<12288, 256, 0, s2>>>(pww, qw, kvw, ow, Wh, Wl);
    cudaEventRecord(evJoin0, s2);

    k_embed<<<B_ * L_, 256>>>(tok, ctab, projw, escale, x);

    for (int i = 0; i < 2; i++) {
        // --- conv block ---
        k_dwconv<<<dim3(64, 4, 2), 256>>>(x, dww + (size_t)i * D_ * 5, dwb + i * D_,
                                          t1h, t1l);

        if (i == 0) cudaStreamWaitEvent(0, evJoin0, 0);   // weights ready

        Batch8 b1; fill1(b1);
        gemm_pp<<<dim3(8, 32, 1), 512, GEMM_SMEM>>>(
            t1h, t1l, Wh + (long long)i * 2097152, Wl + (long long)i * 2097152,
            t2, nullptr, nullptr, pwb + i * 2048, 1024, 1024, 1024, 2048, 64, b1);

        k_glu_ln<<<B_ * L_, 256>>>(x, t2, gbias + i * D_, clng + i * D_, clnb + i * D_,
                                   x, xh, xl);

        // --- attention block ---
        const long long OQKV = 4194304 + (long long)i * 3145728;
        gemm_pp<<<dim3(12, 32, 1), 512, GEMM_SMEM>>>(
            xh, xl, Wh + OQKV, Wl + OQKV,
            nullptr, qkvh, qkvl, nullptr, 1024, 1024, 1024, 3072, 64, b1);

        // fork: V transpose on s2, overlapped with scores GEMM + rowsoft
        cudaEventRecord(evFork1, 0);
        cudaStreamWaitEvent(s2, evFork1, 0);
        k_packv<<<dim3(32, 16, 2), 256, 0, s2>>>(qkvh, qkvl, vth, vtl);
        cudaEventRecord(evJoin1, s2);

        // scores: B = K read directly from qkv planes (chunk kt = head kt, stride 128)
        Batch8 bs; fill1(bs);
        for (int zz = 0; zz < 8; zz++) {
            int bg = zz >> 1, G = zz & 1;
            int b = bg >> 1, g = bg & 1;
            bs.offA[zz] = (long long)b * L_ * 3072 + g * 512;
            bs.offB[zz] = (long long)b * L_ * 3072 + 1024 + (long long)G * 1024;
            bs.offC[zz] = (long long)bg * L_ * 4096 + G * 2048;
            bs.alpha[zz] = 0.125f * (G ? 2.0f : 1.0f);
        }
        gemm_pp<<<dim3(8, 16, 8), 512, GEMM_SMEM>>>(
            qkvh, qkvl, qkvh, qkvl, S, nullptr, nullptr, nullptr,
            512, 3072, 3072, 4096, 128, bs);

        k_rowsoft<<<dim3(L_, 2, 4), 256>>>(S, Ph, Pl);

        cudaStreamWaitEvent(0, evJoin1, 0);   // V transpose ready

        Batch8 bo; fill1(bo);
        for (int zz = 0; zz < 4; zz++) {
            int b = zz >> 1, g = zz & 1;
            bo.offA[zz] = (long long)zz * L_ * 4096;
            bo.offB[zz] = (long long)b * 512 * 4096;
            bo.offC[zz] = (long long)b * L_ * 1024 + g * 512;
        }
        gemm_pp<<<dim3(2, 16, 4), 512, GEMM_SMEM>>>(
            Ph, Pl, vth, vtl, nullptr, t1h, t1l, nullptr, 4096, 4096, 4096, 1024, 64, bo);

        const long long OOW = 10485760 + (long long)i * 1048576;
        gemm_pp<<<dim3(4, 32, 1), 512, GEMM_SMEM>>>(
            t1h, t1l, Wh + OOW, Wl + OOW,
            q, nullptr, nullptr, nullptr, 1024, 1024, 1024, 1024, 64, b1);

        float* dst = (i == 1) ? (float*)d_out : x;
        k_add_ln<<<B_ * L_, 256>>>(x, q, alng + i * D_, alnb + i * D_, dst);
    }
}